// round 1
// baseline (speedup 1.0000x reference)
#include <cuda_runtime.h>
#include <cstdint>

// Problem constants
#define B_  4
#define S_  2048
#define H_  16
#define DK_ 64
#define DM_ 1024
#define M_  (B_ * S_)   // 8192 rows for projections

// Scratch (device globals: allocation-free per harness rules)
__device__ float g_Q[(size_t)B_ * H_ * S_ * DK_];   // [B,H,S,dk]
__device__ float g_K[(size_t)B_ * H_ * S_ * DK_];
__device__ float g_V[(size_t)B_ * H_ * S_ * DK_];
__device__ float g_AO[(size_t)B_ * S_ * DM_];       // [B,S,D] attention output

// ---------------------------------------------------------------------------
// GEMM: Y = X @ W^T + bias.  X:[M,1024] row-major, W:[1024,1024] row-major
// (so Y[m,n] = sum_k X[m,k]*W[n,k] + bias[n]).
// MODE 0: write Y[m,n] at Y[m*1024+n]  (plain [M,N])
// MODE 1: write head-split: m=(b,s), n=(h,d) -> Y[((b*16+h)*2048+s)*64+d]
// Tiling: BM=BN=128, BK=16, 256 threads, 8x8 per thread.
// ---------------------------------------------------------------------------
template <int MODE>
__global__ __launch_bounds__(256, 2)
void gemm_bias_k(const float* __restrict__ A, const float* __restrict__ W,
                 const float* __restrict__ bias, float* __restrict__ Y)
{
    const int K = 1024, N = 1024;
    __shared__ float As[16][128];   // [k][m] transposed
    __shared__ float Bs[16][128];   // [k][n] transposed

    const int tid = threadIdx.x;
    const int tx = tid & 15;        // n-group
    const int ty = tid >> 4;        // m-group
    const int m0 = blockIdx.y * 128;
    const int n0 = blockIdx.x * 128;

    // Load mapping: lane-consecutive rows -> conflict-free transposed stores
    const int lr = tid & 127;       // row within tile
    const int lg = tid >> 7;        // 0..1 -> handles quads lg, lg+2

    const float* Aptr = A + (size_t)(m0 + lr) * K;
    const float* Wptr = W + (size_t)(n0 + lr) * K;

    float acc[8][8];
#pragma unroll
    for (int r = 0; r < 8; r++)
#pragma unroll
        for (int c = 0; c < 8; c++) acc[r][c] = 0.0f;

    for (int k0 = 0; k0 < K; k0 += 16) {
#pragma unroll
        for (int t = 0; t < 2; t++) {
            int q = lg + t * 2;     // 0..3 (quad of k)
            float4 va = *(const float4*)(Aptr + k0 + q * 4);
            As[q * 4 + 0][lr] = va.x;
            As[q * 4 + 1][lr] = va.y;
            As[q * 4 + 2][lr] = va.z;
            As[q * 4 + 3][lr] = va.w;
            float4 vb = *(const float4*)(Wptr + k0 + q * 4);
            Bs[q * 4 + 0][lr] = vb.x;
            Bs[q * 4 + 1][lr] = vb.y;
            Bs[q * 4 + 2][lr] = vb.z;
            Bs[q * 4 + 3][lr] = vb.w;
        }
        __syncthreads();

#pragma unroll
        for (int kk = 0; kk < 16; kk++) {
            float4 a0 = *(const float4*)&As[kk][ty * 8];
            float4 a1 = *(const float4*)&As[kk][ty * 8 + 4];
            float4 b0 = *(const float4*)&Bs[kk][tx * 8];
            float4 b1 = *(const float4*)&Bs[kk][tx * 8 + 4];
            float ar[8] = {a0.x, a0.y, a0.z, a0.w, a1.x, a1.y, a1.z, a1.w};
            float br[8] = {b0.x, b0.y, b0.z, b0.w, b1.x, b1.y, b1.z, b1.w};
#pragma unroll
            for (int r = 0; r < 8; r++)
#pragma unroll
                for (int c = 0; c < 8; c++)
                    acc[r][c] = fmaf(ar[r], br[c], acc[r][c]);
        }
        __syncthreads();
    }

    // Epilogue
#pragma unroll
    for (int r = 0; r < 8; r++) {
        int m = m0 + ty * 8 + r;
#pragma unroll
        for (int cq = 0; cq < 2; cq++) {
            int n = n0 + tx * 8 + cq * 4;
            float4 bv = *(const float4*)&bias[n];
            float4 v;
            v.x = acc[r][cq * 4 + 0] + bv.x;
            v.y = acc[r][cq * 4 + 1] + bv.y;
            v.z = acc[r][cq * 4 + 2] + bv.z;
            v.w = acc[r][cq * 4 + 3] + bv.w;
            if (MODE == 0) {
                *(float4*)&Y[(size_t)m * N + n] = v;
            } else {
                int b = m >> 11;          // m / 2048
                int s = m & 2047;
                int h = n >> 6;           // n / 64
                int d = n & 63;
                *(float4*)&Y[(((size_t)(b * H_ + h) * S_ + s) << 6) + d] = v;
            }
        }
    }
}

// ---------------------------------------------------------------------------
// Flash attention (fp32, causal). grid = (32 q-tiles, 64 b*h). 256 threads.
// Q,K,V in [B,H,S,64]. Output AO in [B,S,1024].
// Tiles: 64 q-rows x 64 kv-cols x d=64. Online softmax.
// Smem: Qt,Kt d-major [64][64]; Vt [j][64]; Sp stride 68. 66560 B dynamic.
// ---------------------------------------------------------------------------
__global__ __launch_bounds__(256, 3)
void attn_k(const float* __restrict__ Q, const float* __restrict__ K,
            const float* __restrict__ V, float* __restrict__ AO)
{
    extern __shared__ float sm[];
    float* Qt = sm;            // [d][i]  stride 64
    float* Kt = sm + 4096;     // [d][j]  stride 64
    float* Vt = sm + 8192;     // [j][d]  stride 64
    float* Sp = sm + 12288;    // [i][j]  stride 68

    const int tid = threadIdx.x;
    const int tx = tid & 15;   // kv / d column group
    const int ty = tid >> 4;   // q row group
    const int qt = blockIdx.x;
    const int bh = blockIdx.y;

    const float* Qb = Q + (size_t)bh * (S_ * DK_);
    const float* Kb = K + (size_t)bh * (S_ * DK_);
    const float* Vb = V + (size_t)bh * (S_ * DK_);

    // Load Q tile transposed (d-major), lane-consecutive i -> no bank conflicts
    {
        int i = tid & 63, g = tid >> 6;   // g in 0..3
        const float* src = Qb + (size_t)(qt * 64 + i) * 64;
#pragma unroll
        for (int t = 0; t < 4; t++) {
            int q = g * 4 + t;            // d-quad 0..15
            float4 v4 = *(const float4*)(src + q * 4);
            Qt[(q * 4 + 0) * 64 + i] = v4.x;
            Qt[(q * 4 + 1) * 64 + i] = v4.y;
            Qt[(q * 4 + 2) * 64 + i] = v4.z;
            Qt[(q * 4 + 3) * 64 + i] = v4.w;
        }
    }

    float m_[4], l_[4], o_[4][4];
#pragma unroll
    for (int r = 0; r < 4; r++) {
        m_[r] = -1e30f;
        l_[r] = 0.0f;
#pragma unroll
        for (int c = 0; c < 4; c++) o_[r][c] = 0.0f;
    }

    for (int kt = 0; kt <= qt; kt++) {
        // Load K tile transposed + V tile direct
        {
            int i = tid & 63, g = tid >> 6;
            const float* src = Kb + (size_t)(kt * 64 + i) * 64;
#pragma unroll
            for (int t = 0; t < 4; t++) {
                int q = g * 4 + t;
                float4 v4 = *(const float4*)(src + q * 4);
                Kt[(q * 4 + 0) * 64 + i] = v4.x;
                Kt[(q * 4 + 1) * 64 + i] = v4.y;
                Kt[(q * 4 + 2) * 64 + i] = v4.z;
                Kt[(q * 4 + 3) * 64 + i] = v4.w;
            }
        }
#pragma unroll
        for (int t = 0; t < 4; t++) {
            int idx = tid + 256 * t;
            int j = idx >> 4, dq = idx & 15;
            *(float4*)&Vt[j * 64 + dq * 4] =
                *(const float4*)(Vb + (size_t)(kt * 64 + j) * 64 + dq * 4);
        }
        __syncthreads();

        // S = Q K^T (4x4 per thread), scaled
        float s[4][4];
#pragma unroll
        for (int r = 0; r < 4; r++)
#pragma unroll
            for (int c = 0; c < 4; c++) s[r][c] = 0.0f;

#pragma unroll 16
        for (int d = 0; d < 64; d++) {
            float4 q4 = *(const float4*)&Qt[d * 64 + ty * 4];
            float4 k4 = *(const float4*)&Kt[d * 64 + tx * 4];
            float qr[4] = {q4.x, q4.y, q4.z, q4.w};
            float kr[4] = {k4.x, k4.y, k4.z, k4.w};
#pragma unroll
            for (int r = 0; r < 4; r++)
#pragma unroll
                for (int c = 0; c < 4; c++)
                    s[r][c] = fmaf(qr[r], kr[c], s[r][c]);
        }

        const float sc = 0.125f;   // 1/sqrt(64)
#pragma unroll
        for (int r = 0; r < 4; r++)
#pragma unroll
            for (int c = 0; c < 4; c++) s[r][c] *= sc;

        if (kt == qt) {
#pragma unroll
            for (int r = 0; r < 4; r++)
#pragma unroll
                for (int c = 0; c < 4; c++)
                    if (tx * 4 + c > ty * 4 + r) s[r][c] = -1e30f;
        }

        // Online softmax per row (16 threads of same ty share a row set)
#pragma unroll
        for (int r = 0; r < 4; r++) {
            float mx = fmaxf(fmaxf(s[r][0], s[r][1]), fmaxf(s[r][2], s[r][3]));
#pragma unroll
            for (int w = 1; w < 16; w <<= 1)
                mx = fmaxf(mx, __shfl_xor_sync(0xffffffffu, mx, w));
            float mnew = fmaxf(m_[r], mx);
            float corr = __expf(m_[r] - mnew);
            float rs = 0.0f;
#pragma unroll
            for (int c = 0; c < 4; c++) {
                float p = __expf(s[r][c] - mnew);
                s[r][c] = p;
                rs += p;
            }
#pragma unroll
            for (int w = 1; w < 16; w <<= 1)
                rs += __shfl_xor_sync(0xffffffffu, rs, w);
            l_[r] = l_[r] * corr + rs;
            m_[r] = mnew;
#pragma unroll
            for (int c = 0; c < 4; c++) o_[r][c] *= corr;
            float4 pv = make_float4(s[r][0], s[r][1], s[r][2], s[r][3]);
            *(float4*)&Sp[(ty * 4 + r) * 68 + tx * 4] = pv;
        }
        __syncthreads();

        // O += P @ V
#pragma unroll 4
        for (int j = 0; j < 64; j += 4) {
            float Pv[4][4];
#pragma unroll
            for (int r = 0; r < 4; r++) {
                float4 p4 = *(const float4*)&Sp[(ty * 4 + r) * 68 + j];
                Pv[r][0] = p4.x; Pv[r][1] = p4.y; Pv[r][2] = p4.z; Pv[r][3] = p4.w;
            }
#pragma unroll
            for (int jj = 0; jj < 4; jj++) {
                float4 v4 = *(const float4*)&Vt[(j + jj) * 64 + tx * 4];
                float vr[4] = {v4.x, v4.y, v4.z, v4.w};
#pragma unroll
                for (int r = 0; r < 4; r++)
#pragma unroll
                    for (int c = 0; c < 4; c++)
                        o_[r][c] = fmaf(Pv[r][jj], vr[c], o_[r][c]);
            }
        }
        __syncthreads();
    }

    // Normalize + write out in [B,S,1024] layout
    const int b = bh >> 4, h = bh & 15;
#pragma unroll
    for (int r = 0; r < 4; r++) {
        float inv = 1.0f / l_[r];
        int srow = qt * 64 + ty * 4 + r;
        float4 v;
        v.x = o_[r][0] * inv;
        v.y = o_[r][1] * inv;
        v.z = o_[r][2] * inv;
        v.w = o_[r][3] * inv;
        *(float4*)&AO[(size_t)(b * S_ + srow) * DM_ + h * 64 + tx * 4] = v;
    }
}

// ---------------------------------------------------------------------------
extern "C" void kernel_launch(void* const* d_in, const int* in_sizes, int n_in,
                              void* d_out, int out_size)
{
    const float* q  = (const float*)d_in[0];
    const float* k  = (const float*)d_in[1];
    const float* v  = (const float*)d_in[2];
    // d_in[3] = mask (deterministic causal tril; handled structurally)
    const float* wq = (const float*)d_in[4];
    const float* bq = (const float*)d_in[5];
    const float* wk = (const float*)d_in[6];
    const float* bk = (const float*)d_in[7];
    const float* wv = (const float*)d_in[8];
    const float* bv = (const float*)d_in[9];
    const float* wo = (const float*)d_in[10];
    const float* bo = (const float*)d_in[11];
    float* out = (float*)d_out;

    float *pQ, *pK, *pV, *pA;
    cudaGetSymbolAddress((void**)&pQ, g_Q);
    cudaGetSymbolAddress((void**)&pK, g_K);
    cudaGetSymbolAddress((void**)&pV, g_V);
    cudaGetSymbolAddress((void**)&pA, g_AO);

    dim3 gg(DM_ / 128, M_ / 128);   // (8, 64)

    gemm_bias_k<1><<<gg, 256>>>(q, wq, bq, pQ);
    gemm_bias_k<1><<<gg, 256>>>(k, wk, bk, pK);
    gemm_bias_k<1><<<gg, 256>>>(v, wv, bv, pV);

    const int attn_smem = (12288 + 64 * 68) * 4;   // 66560 bytes
    cudaFuncSetAttribute(attn_k, cudaFuncAttributeMaxDynamicSharedMemorySize,
                         attn_smem);
    attn_k<<<dim3(S_ / 64, B_ * H_), 256, attn_smem>>>(pQ, pK, pV, pA);

    gemm_bias_k<0><<<gg, 256>>>(pA, wo, bo, out);
}

// round 4
// speedup vs baseline: 1.5037x; 1.5037x over previous
#include <cuda_runtime.h>
#include <cuda_bf16.h>
#include <cstdint>

// Problem constants
#define B_  4
#define S_  2048
#define H_  16
#define DK_ 64
#define DM_ 1024
#define M_  (B_ * S_)   // 8192 rows for projections

// Scratch (device globals: allocation-free per harness rules)
__device__ float g_Q[(size_t)B_ * H_ * S_ * DK_];   // [B,H,S,dk]
__device__ float g_K[(size_t)B_ * H_ * S_ * DK_];
__device__ float g_V[(size_t)B_ * H_ * S_ * DK_];
__device__ float g_AO[(size_t)B_ * S_ * DM_];       // [B,S,D]

// ===========================================================================
// helpers
// ===========================================================================
__device__ __forceinline__ uint32_t smem_u32(const void* p) {
    uint32_t a;
    asm("{ .reg .u64 t; cvta.to.shared.u64 t, %1; cvt.u32.u64 %0, t; }"
        : "=r"(a) : "l"(p));
    return a;
}

#define LDSM_X4(r0, r1, r2, r3, addr)                                        \
    asm volatile("ldmatrix.sync.aligned.m8n8.x4.shared.b16 {%0,%1,%2,%3}, [%4];" \
                 : "=r"(r0), "=r"(r1), "=r"(r2), "=r"(r3) : "r"(addr))

#define MMA_BF16(d, a, B0, B1)                                               \
    asm volatile("mma.sync.aligned.m16n8k16.row.col.f32.bf16.bf16.f32 "      \
                 "{%0,%1,%2,%3}, {%4,%5,%6,%7}, {%8,%9}, {%0,%1,%2,%3};"     \
                 : "+f"((d)[0]), "+f"((d)[1]), "+f"((d)[2]), "+f"((d)[3])    \
                 : "r"((a)[0]), "r"((a)[1]), "r"((a)[2]), "r"((a)[3]),       \
                   "r"(B0), "r"(B1))

// bf16 hi/lo split helpers
__device__ __forceinline__ uint32_t pack_hi(float a, float b, float& ra, float& rb) {
    __nv_bfloat16 ha = __float2bfloat16(a);
    __nv_bfloat16 hb = __float2bfloat16(b);
    ra = a - __bfloat162float(ha);
    rb = b - __bfloat162float(hb);
    __nv_bfloat162 p;
    p.x = ha; p.y = hb;
    return *(uint32_t*)&p;
}
__device__ __forceinline__ uint32_t pack_lo(float ra, float rb) {
    __nv_bfloat162 p;
    p.x = __float2bfloat16(ra);
    p.y = __float2bfloat16(rb);
    return *(uint32_t*)&p;
}

// ===========================================================================
// HMMA GEMM: Y = X @ W^T + bias. X:[8192,1024], W:[1024,1024] row-major.
// bf16 hi/lo 3-term split, fp32 register accumulate.
// Block tile 128x128, K-chunk 64. 8 warps as 4(M) x 2(N); warp tile 32x64.
// Smem tiles: rows padded to 144 bytes (72 bf16) for conflict-free ldmatrix.
// MODE 0: Y[m*1024+n].  MODE 1: head-split [B,H,S,64].
// ===========================================================================
#define ROWB     144                    // bytes per smem tile row
#define OFF_AH   0
#define OFF_AL   (OFF_AH + 128 * ROWB)  // 18432
#define OFF_BH   (OFF_AL + 128 * ROWB)  // 36864
#define OFF_BL   (OFF_BH + 128 * ROWB)  // 55296
#define GEMM_SMEM (OFF_BL + 128 * ROWB) // 73728

template <int MODE>
__global__ __launch_bounds__(256, 2)
void gemm_mma(const float* __restrict__ A, const float* __restrict__ W,
              const float* __restrict__ bias, float* __restrict__ Y)
{
    extern __shared__ char sm[];
    const uint32_t sb = smem_u32(sm);
    const int tid = threadIdx.x;
    const int wid = tid >> 5;
    const int lane = tid & 31;
    const int wm = wid & 3;             // 0..3  (M)
    const int wn = wid >> 2;            // 0..1  (N)
    const int m0 = blockIdx.y * 128;
    const int n0 = blockIdx.x * 128;

    // Global load mapping: row = tid>>1 (0..127), 32 floats per thread
    const int lr = tid >> 1;
    const int cg = (tid & 1) * 32;
    const float* Arow = A + (size_t)(m0 + lr) * 1024 + cg;
    const float* Wrow = W + (size_t)(n0 + lr) * 1024 + cg;
    const uint32_t sto = (uint32_t)(lr * ROWB + cg * 2);

    float acc[2][8][4];
#pragma unroll
    for (int t = 0; t < 2; t++)
#pragma unroll
        for (int j = 0; j < 8; j++)
#pragma unroll
            for (int c = 0; c < 4; c++) acc[t][j][c] = 0.0f;

    // ldmatrix lane address components (constant over loop)
    const uint32_t a_row = (uint32_t)(wm * 32 + (lane & 15));
    const uint32_t a_colb = (uint32_t)((lane >> 4) * 16);      // byte
    const uint32_t b_row = (uint32_t)(wn * 64 + (lane & 7) + ((lane >> 4) & 1) * 8);
    const uint32_t b_colb = (uint32_t)(((lane >> 3) & 1) * 16); // byte

    for (int kc = 0; kc < 16; kc++) {
        // Load f32 chunk, convert to bf16 hi/lo, store swizzle-free (padded rows)
#pragma unroll
        for (int t = 0; t < 8; t++) {
            float4 a4 = *(const float4*)(Arow + kc * 64 + t * 4);
            float4 b4 = *(const float4*)(Wrow + kc * 64 + t * 4);
            float r0, r1, r2, r3;
            uint32_t h01 = pack_hi(a4.x, a4.y, r0, r1);
            uint32_t h23 = pack_hi(a4.z, a4.w, r2, r3);
            *(uint2*)(sm + OFF_AH + sto + t * 8) = make_uint2(h01, h23);
            *(uint2*)(sm + OFF_AL + sto + t * 8) =
                make_uint2(pack_lo(r0, r1), pack_lo(r2, r3));
            h01 = pack_hi(b4.x, b4.y, r0, r1);
            h23 = pack_hi(b4.z, b4.w, r2, r3);
            *(uint2*)(sm + OFF_BH + sto + t * 8) = make_uint2(h01, h23);
            *(uint2*)(sm + OFF_BL + sto + t * 8) =
                make_uint2(pack_lo(r0, r1), pack_lo(r2, r3));
        }
        __syncthreads();

#pragma unroll
        for (int ks = 0; ks < 4; ks++) {
            const uint32_t kb = (uint32_t)(ks * 32);
            uint32_t ah[2][4], al[2][4];
#pragma unroll
            for (int t = 0; t < 2; t++) {
                uint32_t adr = sb + OFF_AH + (a_row + t * 16) * ROWB + kb + a_colb;
                LDSM_X4(ah[t][0], ah[t][1], ah[t][2], ah[t][3], adr);
                adr = sb + OFF_AL + (a_row + t * 16) * ROWB + kb + a_colb;
                LDSM_X4(al[t][0], al[t][1], al[t][2], al[t][3], adr);
            }
#pragma unroll
            for (int p = 0; p < 4; p++) {
                uint32_t bh[4], bl[4];
                uint32_t bdr = sb + OFF_BH + (b_row + p * 16) * ROWB + kb + b_colb;
                LDSM_X4(bh[0], bh[1], bh[2], bh[3], bdr);
                bdr = sb + OFF_BL + (b_row + p * 16) * ROWB + kb + b_colb;
                LDSM_X4(bl[0], bl[1], bl[2], bl[3], bdr);
#pragma unroll
                for (int t = 0; t < 2; t++) {
                    MMA_BF16(acc[t][p * 2 + 0], ah[t], bh[0], bh[1]);
                    MMA_BF16(acc[t][p * 2 + 0], ah[t], bl[0], bl[1]);
                    MMA_BF16(acc[t][p * 2 + 0], al[t], bh[0], bh[1]);
                    MMA_BF16(acc[t][p * 2 + 1], ah[t], bh[2], bh[3]);
                    MMA_BF16(acc[t][p * 2 + 1], ah[t], bl[2], bl[3]);
                    MMA_BF16(acc[t][p * 2 + 1], al[t], bh[2], bh[3]);
                }
            }
        }
        __syncthreads();
    }

    // Epilogue: fragment layout d0,d1 -> row (lane>>2), cols (lane&3)*2,+1;
    // d2,d3 -> row +8.
#pragma unroll
    for (int t = 0; t < 2; t++) {
        const int mrow = m0 + wm * 32 + t * 16 + (lane >> 2);
#pragma unroll
        for (int j = 0; j < 8; j++) {
            const int n = n0 + wn * 64 + j * 8 + (lane & 3) * 2;
            float2 bv = *(const float2*)&bias[n];
            float2 v0, v1;
            v0.x = acc[t][j][0] + bv.x;
            v0.y = acc[t][j][1] + bv.y;
            v1.x = acc[t][j][2] + bv.x;
            v1.y = acc[t][j][3] + bv.y;
            if (MODE == 0) {
                *(float2*)&Y[(size_t)mrow * 1024 + n] = v0;
                *(float2*)&Y[(size_t)(mrow + 8) * 1024 + n] = v1;
            } else {
                int h = n >> 6, d = n & 63;
                int b0i = mrow >> 11, s0 = mrow & 2047;
                *(float2*)&Y[(((size_t)(b0i * H_ + h) * S_ + s0) << 6) + d] = v0;
                int b1i = (mrow + 8) >> 11, s1 = (mrow + 8) & 2047;
                *(float2*)&Y[(((size_t)(b1i * H_ + h) * S_ + s1) << 6) + d] = v1;
            }
        }
    }
}

// ---------------------------------------------------------------------------
// Flash attention (fp32, causal) — unchanged.
// ---------------------------------------------------------------------------
__global__ __launch_bounds__(256, 3)
void attn_k(const float* __restrict__ Q, const float* __restrict__ K,
            const float* __restrict__ V, float* __restrict__ AO)
{
    extern __shared__ float smf[];
    float* Qt = smf;            // [d][i]  stride 64
    float* Kt = smf + 4096;     // [d][j]  stride 64
    float* Vt = smf + 8192;     // [j][d]  stride 64
    float* Sp = smf + 12288;    // [i][j]  stride 68

    const int tid = threadIdx.x;
    const int tx = tid & 15;
    const int ty = tid >> 4;
    const int qt = blockIdx.x;
    const int bh = blockIdx.y;

    const float* Qb = Q + (size_t)bh * (S_ * DK_);
    const float* Kb = K + (size_t)bh * (S_ * DK_);
    const float* Vb = V + (size_t)bh * (S_ * DK_);

    {
        int i = tid & 63, g = tid >> 6;
        const float* src = Qb + (size_t)(qt * 64 + i) * 64;
#pragma unroll
        for (int t = 0; t < 4; t++) {
            int q = g * 4 + t;
            float4 v4 = *(const float4*)(src + q * 4);
            Qt[(q * 4 + 0) * 64 + i] = v4.x;
            Qt[(q * 4 + 1) * 64 + i] = v4.y;
            Qt[(q * 4 + 2) * 64 + i] = v4.z;
            Qt[(q * 4 + 3) * 64 + i] = v4.w;
        }
    }

    float m_[4], l_[4], o_[4][4];
#pragma unroll
    for (int r = 0; r < 4; r++) {
        m_[r] = -1e30f;
        l_[r] = 0.0f;
#pragma unroll
        for (int c = 0; c < 4; c++) o_[r][c] = 0.0f;
    }

    for (int kt = 0; kt <= qt; kt++) {
        {
            int i = tid & 63, g = tid >> 6;
            const float* src = Kb + (size_t)(kt * 64 + i) * 64;
#pragma unroll
            for (int t = 0; t < 4; t++) {
                int q = g * 4 + t;
                float4 v4 = *(const float4*)(src + q * 4);
                Kt[(q * 4 + 0) * 64 + i] = v4.x;
                Kt[(q * 4 + 1) * 64 + i] = v4.y;
                Kt[(q * 4 + 2) * 64 + i] = v4.z;
                Kt[(q * 4 + 3) * 64 + i] = v4.w;
            }
        }
#pragma unroll
        for (int t = 0; t < 4; t++) {
            int idx = tid + 256 * t;
            int j = idx >> 4, dq = idx & 15;
            *(float4*)&Vt[j * 64 + dq * 4] =
                *(const float4*)(Vb + (size_t)(kt * 64 + j) * 64 + dq * 4);
        }
        __syncthreads();

        float s[4][4];
#pragma unroll
        for (int r = 0; r < 4; r++)
#pragma unroll
            for (int c = 0; c < 4; c++) s[r][c] = 0.0f;

#pragma unroll 16
        for (int d = 0; d < 64; d++) {
            float4 q4 = *(const float4*)&Qt[d * 64 + ty * 4];
            float4 k4 = *(const float4*)&Kt[d * 64 + tx * 4];
            float qr[4] = {q4.x, q4.y, q4.z, q4.w};
            float kr[4] = {k4.x, k4.y, k4.z, k4.w};
#pragma unroll
            for (int r = 0; r < 4; r++)
#pragma unroll
                for (int c = 0; c < 4; c++)
                    s[r][c] = fmaf(qr[r], kr[c], s[r][c]);
        }

        const float sc = 0.125f;
#pragma unroll
        for (int r = 0; r < 4; r++)
#pragma unroll
            for (int c = 0; c < 4; c++) s[r][c] *= sc;

        if (kt == qt) {
#pragma unroll
            for (int r = 0; r < 4; r++)
#pragma unroll
                for (int c = 0; c < 4; c++)
                    if (tx * 4 + c > ty * 4 + r) s[r][c] = -1e30f;
        }

#pragma unroll
        for (int r = 0; r < 4; r++) {
            float mx = fmaxf(fmaxf(s[r][0], s[r][1]), fmaxf(s[r][2], s[r][3]));
#pragma unroll
            for (int w = 1; w < 16; w <<= 1)
                mx = fmaxf(mx, __shfl_xor_sync(0xffffffffu, mx, w));
            float mnew = fmaxf(m_[r], mx);
            float corr = __expf(m_[r] - mnew);
            float rs = 0.0f;
#pragma unroll
            for (int c = 0; c < 4; c++) {
                float p = __expf(s[r][c] - mnew);
                s[r][c] = p;
                rs += p;
            }
#pragma unroll
            for (int w = 1; w < 16; w <<= 1)
                rs += __shfl_xor_sync(0xffffffffu, rs, w);
            l_[r] = l_[r] * corr + rs;
            m_[r] = mnew;
#pragma unroll
            for (int c = 0; c < 4; c++) o_[r][c] *= corr;
            float4 pv = make_float4(s[r][0], s[r][1], s[r][2], s[r][3]);
            *(float4*)&Sp[(ty * 4 + r) * 68 + tx * 4] = pv;
        }
        __syncthreads();

#pragma unroll 4
        for (int j = 0; j < 64; j += 4) {
            float Pv[4][4];
#pragma unroll
            for (int r = 0; r < 4; r++) {
                float4 p4 = *(const float4*)&Sp[(ty * 4 + r) * 68 + j];
                Pv[r][0] = p4.x; Pv[r][1] = p4.y; Pv[r][2] = p4.z; Pv[r][3] = p4.w;
            }
#pragma unroll
            for (int jj = 0; jj < 4; jj++) {
                float4 v4 = *(const float4*)&Vt[(j + jj) * 64 + tx * 4];
                float vr[4] = {v4.x, v4.y, v4.z, v4.w};
#pragma unroll
                for (int r = 0; r < 4; r++)
#pragma unroll
                    for (int c = 0; c < 4; c++)
                        o_[r][c] = fmaf(Pv[r][jj], vr[c], o_[r][c]);
            }
        }
        __syncthreads();
    }

    const int b = bh >> 4, h = bh & 15;
#pragma unroll
    for (int r = 0; r < 4; r++) {
        float inv = 1.0f / l_[r];
        int srow = qt * 64 + ty * 4 + r;
        float4 v;
        v.x = o_[r][0] * inv;
        v.y = o_[r][1] * inv;
        v.z = o_[r][2] * inv;
        v.w = o_[r][3] * inv;
        *(float4*)&AO[(size_t)(b * S_ + srow) * DM_ + h * 64 + tx * 4] = v;
    }
}

// ---------------------------------------------------------------------------
extern "C" void kernel_launch(void* const* d_in, const int* in_sizes, int n_in,
                              void* d_out, int out_size)
{
    const float* q  = (const float*)d_in[0];
    const float* k  = (const float*)d_in[1];
    const float* v  = (const float*)d_in[2];
    // d_in[3] = mask (deterministic causal tril; handled structurally)
    const float* wq = (const float*)d_in[4];
    const float* bq = (const float*)d_in[5];
    const float* wk = (const float*)d_in[6];
    const float* bk = (const float*)d_in[7];
    const float* wv = (const float*)d_in[8];
    const float* bv = (const float*)d_in[9];
    const float* wo = (const float*)d_in[10];
    const float* bo = (const float*)d_in[11];
    float* out = (float*)d_out;

    float *pQ, *pK, *pV, *pA;
    cudaGetSymbolAddress((void**)&pQ, g_Q);
    cudaGetSymbolAddress((void**)&pK, g_K);
    cudaGetSymbolAddress((void**)&pV, g_V);
    cudaGetSymbolAddress((void**)&pA, g_AO);

    static bool attr_done = false;
    if (!attr_done) {
        cudaFuncSetAttribute(gemm_mma<0>, cudaFuncAttributeMaxDynamicSharedMemorySize,
                             GEMM_SMEM);
        cudaFuncSetAttribute(gemm_mma<1>, cudaFuncAttributeMaxDynamicSharedMemorySize,
                             GEMM_SMEM);
        cudaFuncSetAttribute(attn_k, cudaFuncAttributeMaxDynamicSharedMemorySize,
                             (12288 + 64 * 68) * 4);
        attr_done = true;
    }

    dim3 gg(DM_ / 128, M_ / 128);   // (8, 64)

    gemm_mma<1><<<gg, 256, GEMM_SMEM>>>(q, wq, bq, pQ);
    gemm_mma<1><<<gg, 256, GEMM_SMEM>>>(k, wk, bk, pK);
    gemm_mma<1><<<gg, 256, GEMM_SMEM>>>(v, wv, bv, pV);

    const int attn_smem = (12288 + 64 * 68) * 4;   // 66560 bytes
    attn_k<<<dim3(S_ / 64, B_ * H_), 256, attn_smem>>>(pQ, pK, pV, pA);

    gemm_mma<0><<<gg, 256, GEMM_SMEM>>>(pA, wo, bo, out);
}

// round 10
// speedup vs baseline: 2.1200x; 1.4099x over previous
#include <cuda_runtime.h>
#include <cuda_bf16.h>
#include <cstdint>

// Problem constants
#define B_  4
#define S_  2048
#define H_  16
#define DK_ 64
#define DM_ 1024
#define M_  (B_ * S_)   // 8192 rows for projections

// Scratch (device globals: allocation-free per harness rules)
__device__ float g_Q[(size_t)B_ * H_ * S_ * DK_];   // [B,H,S,dk]
__device__ float g_K[(size_t)B_ * H_ * S_ * DK_];
__device__ float g_V[(size_t)B_ * H_ * S_ * DK_];
__device__ float g_AO[(size_t)B_ * S_ * DM_];       // [B,S,D]

// ===========================================================================
// helpers
// ===========================================================================
__device__ __forceinline__ uint32_t smem_u32(const void* p) {
    uint32_t a;
    asm("{ .reg .u64 t; cvta.to.shared.u64 t, %1; cvt.u32.u64 %0, t; }"
        : "=r"(a) : "l"(p));
    return a;
}

#define LDSM_X4(r0, r1, r2, r3, addr)                                        \
    asm volatile("ldmatrix.sync.aligned.m8n8.x4.shared.b16 {%0,%1,%2,%3}, [%4];" \
                 : "=r"(r0), "=r"(r1), "=r"(r2), "=r"(r3) : "r"(addr))

#define MMA_BF16(d, a, B0, B1)                                               \
    asm volatile("mma.sync.aligned.m16n8k16.row.col.f32.bf16.bf16.f32 "      \
                 "{%0,%1,%2,%3}, {%4,%5,%6,%7}, {%8,%9}, {%0,%1,%2,%3};"     \
                 : "+f"((d)[0]), "+f"((d)[1]), "+f"((d)[2]), "+f"((d)[3])    \
                 : "r"((a)[0]), "r"((a)[1]), "r"((a)[2]), "r"((a)[3]),       \
                   "r"(B0), "r"(B1))

// bf16 hi/lo split helpers
__device__ __forceinline__ uint32_t pack_hi(float a, float b, float& ra, float& rb) {
    __nv_bfloat16 ha = __float2bfloat16(a);
    __nv_bfloat16 hb = __float2bfloat16(b);
    ra = a - __bfloat162float(ha);
    rb = b - __bfloat162float(hb);
    __nv_bfloat162 p;
    p.x = ha; p.y = hb;
    return *(uint32_t*)&p;
}
__device__ __forceinline__ uint32_t pack_lo(float ra, float rb) {
    __nv_bfloat162 p;
    p.x = __float2bfloat16(ra);
    p.y = __float2bfloat16(rb);
    return *(uint32_t*)&p;
}

// ===========================================================================
// HMMA GEMM: Y = X @ W^T + bias (unchanged from round 4, passing).
// ===========================================================================
#define ROWB     144                    // bytes per smem tile row
#define OFF_AH   0
#define OFF_AL   (OFF_AH + 128 * ROWB)  // 18432
#define OFF_BH   (OFF_AL + 128 * ROWB)  // 36864
#define OFF_BL   (OFF_BH + 128 * ROWB)  // 55296
#define GEMM_SMEM (OFF_BL + 128 * ROWB) // 73728

template <int MODE>
__global__ __launch_bounds__(256, 2)
void gemm_mma(const float* __restrict__ A, const float* __restrict__ W,
              const float* __restrict__ bias, float* __restrict__ Y)
{
    extern __shared__ char sm[];
    const uint32_t sb = smem_u32(sm);
    const int tid = threadIdx.x;
    const int wid = tid >> 5;
    const int lane = tid & 31;
    const int wm = wid & 3;             // 0..3  (M)
    const int wn = wid >> 2;            // 0..1  (N)
    const int m0 = blockIdx.y * 128;
    const int n0 = blockIdx.x * 128;

    const int lr = tid >> 1;
    const int cg = (tid & 1) * 32;
    const float* Arow = A + (size_t)(m0 + lr) * 1024 + cg;
    const float* Wrow = W + (size_t)(n0 + lr) * 1024 + cg;
    const uint32_t sto = (uint32_t)(lr * ROWB + cg * 2);

    float acc[2][8][4];
#pragma unroll
    for (int t = 0; t < 2; t++)
#pragma unroll
        for (int j = 0; j < 8; j++)
#pragma unroll
            for (int c = 0; c < 4; c++) acc[t][j][c] = 0.0f;

    const uint32_t a_row = (uint32_t)(wm * 32 + (lane & 15));
    const uint32_t a_colb = (uint32_t)((lane >> 4) * 16);
    const uint32_t b_row = (uint32_t)(wn * 64 + (lane & 7) + ((lane >> 4) & 1) * 8);
    const uint32_t b_colb = (uint32_t)(((lane >> 3) & 1) * 16);

    for (int kc = 0; kc < 16; kc++) {
#pragma unroll
        for (int t = 0; t < 8; t++) {
            float4 a4 = *(const float4*)(Arow + kc * 64 + t * 4);
            float4 b4 = *(const float4*)(Wrow + kc * 64 + t * 4);
            float r0, r1, r2, r3;
            uint32_t h01 = pack_hi(a4.x, a4.y, r0, r1);
            uint32_t h23 = pack_hi(a4.z, a4.w, r2, r3);
            *(uint2*)(sm + OFF_AH + sto + t * 8) = make_uint2(h01, h23);
            *(uint2*)(sm + OFF_AL + sto + t * 8) =
                make_uint2(pack_lo(r0, r1), pack_lo(r2, r3));
            h01 = pack_hi(b4.x, b4.y, r0, r1);
            h23 = pack_hi(b4.z, b4.w, r2, r3);
            *(uint2*)(sm + OFF_BH + sto + t * 8) = make_uint2(h01, h23);
            *(uint2*)(sm + OFF_BL + sto + t * 8) =
                make_uint2(pack_lo(r0, r1), pack_lo(r2, r3));
        }
        __syncthreads();

#pragma unroll
        for (int ks = 0; ks < 4; ks++) {
            const uint32_t kb = (uint32_t)(ks * 32);
            uint32_t ah[2][4], al[2][4];
#pragma unroll
            for (int t = 0; t < 2; t++) {
                uint32_t adr = sb + OFF_AH + (a_row + t * 16) * ROWB + kb + a_colb;
                LDSM_X4(ah[t][0], ah[t][1], ah[t][2], ah[t][3], adr);
                adr = sb + OFF_AL + (a_row + t * 16) * ROWB + kb + a_colb;
                LDSM_X4(al[t][0], al[t][1], al[t][2], al[t][3], adr);
            }
#pragma unroll
            for (int p = 0; p < 4; p++) {
                uint32_t bh[4], bl[4];
                uint32_t bdr = sb + OFF_BH + (b_row + p * 16) * ROWB + kb + b_colb;
                LDSM_X4(bh[0], bh[1], bh[2], bh[3], bdr);
                bdr = sb + OFF_BL + (b_row + p * 16) * ROWB + kb + b_colb;
                LDSM_X4(bl[0], bl[1], bl[2], bl[3], bdr);
#pragma unroll
                for (int t = 0; t < 2; t++) {
                    MMA_BF16(acc[t][p * 2 + 0], ah[t], bh[0], bh[1]);
                    MMA_BF16(acc[t][p * 2 + 0], ah[t], bl[0], bl[1]);
                    MMA_BF16(acc[t][p * 2 + 0], al[t], bh[0], bh[1]);
                    MMA_BF16(acc[t][p * 2 + 1], ah[t], bh[2], bh[3]);
                    MMA_BF16(acc[t][p * 2 + 1], ah[t], bl[2], bl[3]);
                    MMA_BF16(acc[t][p * 2 + 1], al[t], bh[2], bh[3]);
                }
            }
        }
        __syncthreads();
    }

#pragma unroll
    for (int t = 0; t < 2; t++) {
        const int mrow = m0 + wm * 32 + t * 16 + (lane >> 2);
#pragma unroll
        for (int j = 0; j < 8; j++) {
            const int n = n0 + wn * 64 + j * 8 + (lane & 3) * 2;
            float2 bv = *(const float2*)&bias[n];
            float2 v0, v1;
            v0.x = acc[t][j][0] + bv.x;
            v0.y = acc[t][j][1] + bv.y;
            v1.x = acc[t][j][2] + bv.x;
            v1.y = acc[t][j][3] + bv.y;
            if (MODE == 0) {
                *(float2*)&Y[(size_t)mrow * 1024 + n] = v0;
                *(float2*)&Y[(size_t)(mrow + 8) * 1024 + n] = v1;
            } else {
                int h = n >> 6, d = n & 63;
                int b0i = mrow >> 11, s0 = mrow & 2047;
                *(float2*)&Y[(((size_t)(b0i * H_ + h) * S_ + s0) << 6) + d] = v0;
                int b1i = (mrow + 8) >> 11, s1 = (mrow + 8) & 2047;
                *(float2*)&Y[(((size_t)(b1i * H_ + h) * S_ + s1) << 6) + d] = v1;
            }
        }
    }
}

// ===========================================================================
// Flash attention via HMMA (bf16 hi/lo 3-term split, fp32 accum, causal).
// Block: 256 threads = 8 warps; q-tile 128 rows, kv-tile 64.
// Each warp owns 16 q-rows x full kv width (softmax rows stay in-warp).
// Q pre-scaled by 0.125 (exact) before split.
// Smem: Qh/Ql [128][72bf16], Kh/Kl [64][72], Vt hi/lo [d=64][72] (transposed).
// ===========================================================================
#define A_QH 0
#define A_QL (A_QH + 128 * ROWB)        // 18432
#define A_KH (A_QL + 128 * ROWB)        // 36864
#define A_KL (A_KH + 64 * ROWB)         // 46080
#define A_VH (A_KL + 64 * ROWB)         // 55296
#define A_VL (A_VH + 64 * ROWB)         // 64512
#define ATTN_SMEM (A_VL + 64 * ROWB)    // 73728

__global__ __launch_bounds__(256)
void attn_mma(const float* __restrict__ Q, const float* __restrict__ K,
              const float* __restrict__ V, float* __restrict__ AO)
{
    extern __shared__ char sm[];
    const uint32_t sb = smem_u32(sm);
    const int tid = threadIdx.x;
    const int wid = tid >> 5;
    const int lane = tid & 31;
    const int q0 = blockIdx.x * 128;
    const int bh = blockIdx.y;

    const float* Qb = Q + (size_t)bh * (S_ * DK_);
    const float* Kb = K + (size_t)bh * (S_ * DK_);
    const float* Vb = V + (size_t)bh * (S_ * DK_);

    // Stage Q tile (scaled by 1/8, exact) as hi/lo bf16
    {
        const int lr = tid >> 1, cg = (tid & 1) * 32;
        const float* src = Qb + (size_t)(q0 + lr) * 64 + cg;
        const uint32_t sto = (uint32_t)(lr * ROWB + cg * 2);
#pragma unroll
        for (int t = 0; t < 8; t++) {
            float4 a4 = *(const float4*)(src + t * 4);
            a4.x *= 0.125f; a4.y *= 0.125f; a4.z *= 0.125f; a4.w *= 0.125f;
            float r0, r1, r2, r3;
            uint32_t h01 = pack_hi(a4.x, a4.y, r0, r1);
            uint32_t h23 = pack_hi(a4.z, a4.w, r2, r3);
            *(uint2*)(sm + A_QH + sto + t * 8) = make_uint2(h01, h23);
            *(uint2*)(sm + A_QL + sto + t * 8) =
                make_uint2(pack_lo(r0, r1), pack_lo(r2, r3));
        }
    }
    __syncthreads();

    // Per-warp persistent Q fragments (4 k-steps over d=64)
    const int wr0 = wid * 16;
    uint32_t qh[4][4], ql[4][4];
    {
        const uint32_t base =
            sb + A_QH + (uint32_t)(wr0 + (lane & 15)) * ROWB + (lane >> 4) * 16;
#pragma unroll
        for (int t = 0; t < 4; t++) {
            LDSM_X4(qh[t][0], qh[t][1], qh[t][2], qh[t][3], base + t * 32);
            LDSM_X4(ql[t][0], ql[t][1], ql[t][2], ql[t][3],
                    base + (A_QL - A_QH) + t * 32);
        }
    }

    float m0 = -1e30f, m1 = -1e30f, l0 = 0.0f, l1 = 0.0f;
    float oc[8][4];
#pragma unroll
    for (int n = 0; n < 8; n++)
#pragma unroll
        for (int c = 0; c < 4; c++) oc[n][c] = 0.0f;

    const uint32_t b_row = (uint32_t)((lane & 7) + ((lane >> 4) & 1) * 8);
    const uint32_t b_colb = (uint32_t)(((lane >> 3) & 1) * 16);
    const int row0 = q0 + wr0 + (lane >> 2);

    const int nkt = (q0 >> 6) + 2;     // kv tiles covering cols 0..q0+127
    for (int kt = 0; kt < nkt; kt++) {
        const int kv0 = kt * 64;

        // Load K tile [64 j][64 d] hi/lo
        {
            const int lr = tid >> 2, cg = (tid & 3) * 16;
            const float* src = Kb + (size_t)(kv0 + lr) * 64 + cg;
            const uint32_t sto = (uint32_t)(lr * ROWB + cg * 2);
#pragma unroll
            for (int t = 0; t < 4; t++) {
                float4 a4 = *(const float4*)(src + t * 4);
                float r0, r1, r2, r3;
                uint32_t h01 = pack_hi(a4.x, a4.y, r0, r1);
                uint32_t h23 = pack_hi(a4.z, a4.w, r2, r3);
                *(uint2*)(sm + A_KH + sto + t * 8) = make_uint2(h01, h23);
                *(uint2*)(sm + A_KL + sto + t * 8) =
                    make_uint2(pack_lo(r0, r1), pack_lo(r2, r3));
            }
        }
        // Load V tile transposed: Vt[d][j] hi/lo
        {
            const int j = tid & 63, d0 = (tid >> 6) * 16;
            const float* src = Vb + (size_t)(kv0 + j) * 64 + d0;
#pragma unroll
            for (int i = 0; i < 4; i++) {
                float4 v4 = *(const float4*)(src + i * 4);
                float vv[4] = {v4.x, v4.y, v4.z, v4.w};
#pragma unroll
                for (int e = 0; e < 4; e++) {
                    const int d = d0 + i * 4 + e;
                    __nv_bfloat16 hh = __float2bfloat16(vv[e]);
                    float rr = vv[e] - __bfloat162float(hh);
                    *(__nv_bfloat16*)(sm + A_VH + d * ROWB + j * 2) = hh;
                    *(__nv_bfloat16*)(sm + A_VL + d * ROWB + j * 2) =
                        __float2bfloat16(rr);
                }
            }
        }
        __syncthreads();

        if (kv0 <= q0 + wr0 + 15) {     // warp has at least one unmasked element
            // S = Q K^T (3-term split)
            float sc[8][4];
#pragma unroll
            for (int n = 0; n < 8; n++)
#pragma unroll
                for (int c = 0; c < 4; c++) sc[n][c] = 0.0f;

#pragma unroll
            for (int t = 0; t < 4; t++) {
#pragma unroll
                for (int pp = 0; pp < 4; pp++) {
                    uint32_t kb0, kb1, kb2, kb3, kl0, kl1, kl2, kl3;
                    uint32_t adr =
                        sb + A_KH + (pp * 16 + b_row) * ROWB + t * 32 + b_colb;
                    LDSM_X4(kb0, kb1, kb2, kb3, adr);
                    LDSM_X4(kl0, kl1, kl2, kl3, adr + (A_KL - A_KH));
                    MMA_BF16(sc[pp * 2 + 0], qh[t], kb0, kb1);
                    MMA_BF16(sc[pp * 2 + 0], qh[t], kl0, kl1);
                    MMA_BF16(sc[pp * 2 + 0], ql[t], kb0, kb1);
                    MMA_BF16(sc[pp * 2 + 1], qh[t], kb2, kb3);
                    MMA_BF16(sc[pp * 2 + 1], qh[t], kl2, kl3);
                    MMA_BF16(sc[pp * 2 + 1], ql[t], kb2, kb3);
                }
            }

            // Causal mask on diagonal-overlapping tiles
            if (kv0 + 63 > q0 + wr0) {
#pragma unroll
                for (int n = 0; n < 8; n++) {
                    const int col = kv0 + n * 8 + (lane & 3) * 2;
                    if (col > row0)         sc[n][0] = -1e30f;
                    if (col + 1 > row0)     sc[n][1] = -1e30f;
                    if (col > row0 + 8)     sc[n][2] = -1e30f;
                    if (col + 1 > row0 + 8) sc[n][3] = -1e30f;
                }
            }

            // Online softmax (rows live in 4-lane groups)
            float mx0 = -1e30f, mx1 = -1e30f;
#pragma unroll
            for (int n = 0; n < 8; n++) {
                mx0 = fmaxf(mx0, fmaxf(sc[n][0], sc[n][1]));
                mx1 = fmaxf(mx1, fmaxf(sc[n][2], sc[n][3]));
            }
            mx0 = fmaxf(mx0, __shfl_xor_sync(0xffffffffu, mx0, 1));
            mx0 = fmaxf(mx0, __shfl_xor_sync(0xffffffffu, mx0, 2));
            mx1 = fmaxf(mx1, __shfl_xor_sync(0xffffffffu, mx1, 1));
            mx1 = fmaxf(mx1, __shfl_xor_sync(0xffffffffu, mx1, 2));

            const float mn0 = fmaxf(m0, mx0), mn1 = fmaxf(m1, mx1);
            const float corr0 = __expf(m0 - mn0), corr1 = __expf(m1 - mn1);
            float rs0 = 0.0f, rs1 = 0.0f;
#pragma unroll
            for (int n = 0; n < 8; n++) {
                sc[n][0] = __expf(sc[n][0] - mn0);
                sc[n][1] = __expf(sc[n][1] - mn0);
                sc[n][2] = __expf(sc[n][2] - mn1);
                sc[n][3] = __expf(sc[n][3] - mn1);
                rs0 += sc[n][0] + sc[n][1];
                rs1 += sc[n][2] + sc[n][3];
            }
            rs0 += __shfl_xor_sync(0xffffffffu, rs0, 1);
            rs0 += __shfl_xor_sync(0xffffffffu, rs0, 2);
            rs1 += __shfl_xor_sync(0xffffffffu, rs1, 1);
            rs1 += __shfl_xor_sync(0xffffffffu, rs1, 2);
            l0 = l0 * corr0 + rs0;  m0 = mn0;
            l1 = l1 * corr1 + rs1;  m1 = mn1;
#pragma unroll
            for (int n = 0; n < 8; n++) {
                oc[n][0] *= corr0;  oc[n][1] *= corr0;
                oc[n][2] *= corr1;  oc[n][3] *= corr1;
            }

            // O += P V  (P hi/lo from S fragments; V from transposed smem)
#pragma unroll
            for (int t = 0; t < 4; t++) {
                uint32_t ph[4], pl[4];
                float ra, rb;
                ph[0] = pack_hi(sc[2 * t][0], sc[2 * t][1], ra, rb);
                pl[0] = pack_lo(ra, rb);
                ph[1] = pack_hi(sc[2 * t][2], sc[2 * t][3], ra, rb);
                pl[1] = pack_lo(ra, rb);
                ph[2] = pack_hi(sc[2 * t + 1][0], sc[2 * t + 1][1], ra, rb);
                pl[2] = pack_lo(ra, rb);
                ph[3] = pack_hi(sc[2 * t + 1][2], sc[2 * t + 1][3], ra, rb);
                pl[3] = pack_lo(ra, rb);
#pragma unroll
                for (int pp = 0; pp < 4; pp++) {
                    uint32_t vh0, vh1, vh2, vh3, vl0, vl1, vl2, vl3;
                    uint32_t adr =
                        sb + A_VH + (pp * 16 + b_row) * ROWB + t * 32 + b_colb;
                    LDSM_X4(vh0, vh1, vh2, vh3, adr);
                    LDSM_X4(vl0, vl1, vl2, vl3, adr + (A_VL - A_VH));
                    MMA_BF16(oc[pp * 2 + 0], ph, vh0, vh1);
                    MMA_BF16(oc[pp * 2 + 0], ph, vl0, vl1);
                    MMA_BF16(oc[pp * 2 + 0], pl, vh0, vh1);
                    MMA_BF16(oc[pp * 2 + 1], ph, vh2, vh3);
                    MMA_BF16(oc[pp * 2 + 1], ph, vl2, vl3);
                    MMA_BF16(oc[pp * 2 + 1], pl, vh2, vh3);
                }
            }
        }
        __syncthreads();
    }

    // Epilogue: normalize + write to [B,S,1024] at this head's column block
    const int b = bh >> 4, h = bh & 15;
    const float inv0 = 1.0f / l0, inv1 = 1.0f / l1;
#pragma unroll
    for (int n = 0; n < 8; n++) {
        const int d = h * 64 + n * 8 + (lane & 3) * 2;
        float2 v0 = make_float2(oc[n][0] * inv0, oc[n][1] * inv0);
        float2 v1 = make_float2(oc[n][2] * inv1, oc[n][3] * inv1);
        *(float2*)&AO[(size_t)(b * S_ + row0) * DM_ + d] = v0;
        *(float2*)&AO[(size_t)(b * S_ + row0 + 8) * DM_ + d] = v1;
    }
}

// ---------------------------------------------------------------------------
extern "C" void kernel_launch(void* const* d_in, const int* in_sizes, int n_in,
                              void* d_out, int out_size)
{
    const float* q  = (const float*)d_in[0];
    const float* k  = (const float*)d_in[1];
    const float* v  = (const float*)d_in[2];
    // d_in[3] = mask (deterministic causal tril; handled structurally)
    const float* wq = (const float*)d_in[4];
    const float* bq = (const float*)d_in[5];
    const float* wk = (const float*)d_in[6];
    const float* bk = (const float*)d_in[7];
    const float* wv = (const float*)d_in[8];
    const float* bv = (const float*)d_in[9];
    const float* wo = (const float*)d_in[10];
    const float* bo = (const float*)d_in[11];
    float* out = (float*)d_out;

    float *pQ, *pK, *pV, *pA;
    cudaGetSymbolAddress((void**)&pQ, g_Q);
    cudaGetSymbolAddress((void**)&pK, g_K);
    cudaGetSymbolAddress((void**)&pV, g_V);
    cudaGetSymbolAddress((void**)&pA, g_AO);

    static bool attr_done = false;
    if (!attr_done) {
        cudaFuncSetAttribute(gemm_mma<0>, cudaFuncAttributeMaxDynamicSharedMemorySize,
                             GEMM_SMEM);
        cudaFuncSetAttribute(gemm_mma<1>, cudaFuncAttributeMaxDynamicSharedMemorySize,
                             GEMM_SMEM);
        cudaFuncSetAttribute(attn_mma, cudaFuncAttributeMaxDynamicSharedMemorySize,
                             ATTN_SMEM);
        attr_done = true;
    }

    dim3 gg(DM_ / 128, M_ / 128);   // (8, 64)

    gemm_mma<1><<<gg, 256, GEMM_SMEM>>>(q, wq, bq, pQ);
    gemm_mma<1><<<gg, 256, GEMM_SMEM>>>(k, wk, bk, pK);
    gemm_mma<1><<<gg, 256, GEMM_SMEM>>>(v, wv, bv, pV);

    attn_mma<<<dim3(S_ / 128, B_ * H_), 256, ATTN_SMEM>>>(pQ, pK, pV, pA);

    gemm_mma<0><<<gg, 256, GEMM_SMEM>>>(pA, wo, bo, out);
}

// round 11
// speedup vs baseline: 2.3211x; 1.0948x over previous
#include <cuda_runtime.h>
#include <cuda_bf16.h>
#include <cstdint>

// Problem constants
#define B_  4
#define S_  2048
#define H_  16
#define DK_ 64
#define DM_ 1024
#define M_  (B_ * S_)   // 8192 rows for projections

// Scratch (device globals: allocation-free per harness rules)
__device__ float g_Q[(size_t)B_ * H_ * S_ * DK_];   // [B,H,S,dk]
__device__ float g_K[(size_t)B_ * H_ * S_ * DK_];
__device__ float g_V[(size_t)B_ * H_ * S_ * DK_];
__device__ float g_AO[(size_t)B_ * S_ * DM_];       // [B,S,D]
// bf16 hi/lo staging for GEMM operands (reused across the 4 sequential GEMMs)
__device__ __nv_bfloat16 g_Xh[(size_t)M_ * DM_];
__device__ __nv_bfloat16 g_Xl[(size_t)M_ * DM_];
__device__ __nv_bfloat16 g_Wh[(size_t)DM_ * DM_];
__device__ __nv_bfloat16 g_Wl[(size_t)DM_ * DM_];

// ===========================================================================
// helpers
// ===========================================================================
__device__ __forceinline__ uint32_t smem_u32(const void* p) {
    uint32_t a;
    asm("{ .reg .u64 t; cvta.to.shared.u64 t, %1; cvt.u32.u64 %0, t; }"
        : "=r"(a) : "l"(p));
    return a;
}

#define LDSM_X4(r0, r1, r2, r3, addr)                                        \
    asm volatile("ldmatrix.sync.aligned.m8n8.x4.shared.b16 {%0,%1,%2,%3}, [%4];" \
                 : "=r"(r0), "=r"(r1), "=r"(r2), "=r"(r3) : "r"(addr))

#define MMA_BF16(d, a, B0, B1)                                               \
    asm volatile("mma.sync.aligned.m16n8k16.row.col.f32.bf16.bf16.f32 "      \
                 "{%0,%1,%2,%3}, {%4,%5,%6,%7}, {%8,%9}, {%0,%1,%2,%3};"     \
                 : "+f"((d)[0]), "+f"((d)[1]), "+f"((d)[2]), "+f"((d)[3])    \
                 : "r"((a)[0]), "r"((a)[1]), "r"((a)[2]), "r"((a)[3]),       \
                   "r"(B0), "r"(B1))

// bf16 hi/lo split helpers
__device__ __forceinline__ uint32_t pack_hi(float a, float b, float& ra, float& rb) {
    __nv_bfloat16 ha = __float2bfloat16(a);
    __nv_bfloat16 hb = __float2bfloat16(b);
    ra = a - __bfloat162float(ha);
    rb = b - __bfloat162float(hb);
    __nv_bfloat162 p;
    p.x = ha; p.y = hb;
    return *(uint32_t*)&p;
}
__device__ __forceinline__ uint32_t pack_lo(float ra, float rb) {
    __nv_bfloat162 p;
    p.x = __float2bfloat16(ra);
    p.y = __float2bfloat16(rb);
    return *(uint32_t*)&p;
}

// ===========================================================================
// split_k: fp32 -> bf16 hi/lo arrays (memory-bound pre-pass).
// ===========================================================================
__global__ __launch_bounds__(256)
void split_k(const float* __restrict__ src, __nv_bfloat16* __restrict__ hi,
             __nv_bfloat16* __restrict__ lo, int n4)
{
    int i = blockIdx.x * blockDim.x + threadIdx.x;
    if (i < n4) {
        float4 v = ((const float4*)src)[i];
        float r0, r1, r2, r3;
        uint32_t h01 = pack_hi(v.x, v.y, r0, r1);
        uint32_t h23 = pack_hi(v.z, v.w, r2, r3);
        ((uint2*)hi)[i] = make_uint2(h01, h23);
        ((uint2*)lo)[i] = make_uint2(pack_lo(r0, r1), pack_lo(r2, r3));
    }
}

// ===========================================================================
// HMMA GEMM on pre-split bf16 operands: Y = X @ W^T + bias.
// Block tile 128x128, K-chunk 64, 8 warps (4M x 2N), warp tile 32x64.
// Mainloop is pure LDG.128 -> STS.128 staging + ldmatrix + mma (no CVT).
// MODE 0: Y[m*1024+n].  MODE 1: head-split [B,H,S,64].
// ===========================================================================
#define ROWB     144                    // bytes per smem tile row
#define OFF_AH   0
#define OFF_AL   (OFF_AH + 128 * ROWB)  // 18432
#define OFF_BH   (OFF_AL + 128 * ROWB)  // 36864
#define OFF_BL   (OFF_BH + 128 * ROWB)  // 55296
#define GEMM_SMEM (OFF_BL + 128 * ROWB) // 73728

template <int MODE>
__global__ __launch_bounds__(256, 2)
void gemm_mma(const __nv_bfloat16* __restrict__ Ah,
              const __nv_bfloat16* __restrict__ Al,
              const __nv_bfloat16* __restrict__ Wh,
              const __nv_bfloat16* __restrict__ Wl,
              const float* __restrict__ bias, float* __restrict__ Y)
{
    extern __shared__ char sm[];
    const uint32_t sb = smem_u32(sm);
    const int tid = threadIdx.x;
    const int wid = tid >> 5;
    const int lane = tid & 31;
    const int wm = wid & 3;             // 0..3  (M)
    const int wn = wid >> 2;            // 0..1  (N)
    const int m0 = blockIdx.y * 128;
    const int n0 = blockIdx.x * 128;

    // Global staging mapping: row = tid>>1 (0..127), 32 bf16 per thread/tile
    const int lr = tid >> 1;
    const int cg = (tid & 1) * 32;      // element offset within row chunk
    const uint4* pAh = (const uint4*)(Ah + (size_t)(m0 + lr) * 1024 + cg);
    const uint4* pAl = (const uint4*)(Al + (size_t)(m0 + lr) * 1024 + cg);
    const uint4* pWh = (const uint4*)(Wh + (size_t)(n0 + lr) * 1024 + cg);
    const uint4* pWl = (const uint4*)(Wl + (size_t)(n0 + lr) * 1024 + cg);
    const uint32_t sto = (uint32_t)(lr * ROWB + cg * 2);

    float acc[2][8][4];
#pragma unroll
    for (int t = 0; t < 2; t++)
#pragma unroll
        for (int j = 0; j < 8; j++)
#pragma unroll
            for (int c = 0; c < 4; c++) acc[t][j][c] = 0.0f;

    const uint32_t a_row = (uint32_t)(wm * 32 + (lane & 15));
    const uint32_t a_colb = (uint32_t)((lane >> 4) * 16);
    const uint32_t b_row = (uint32_t)(wn * 64 + (lane & 7) + ((lane >> 4) & 1) * 8);
    const uint32_t b_colb = (uint32_t)(((lane >> 3) & 1) * 16);

    for (int kc = 0; kc < 16; kc++) {
        // Stage chunk kc: 4 x uint4 per tile per thread (64 bytes), no math.
        const int g0 = kc * 8;          // kc*64 elems = kc*8 uint4
#pragma unroll
        for (int t = 0; t < 4; t++) {
            *(uint4*)(sm + OFF_AH + sto + t * 16) = pAh[g0 + t];
            *(uint4*)(sm + OFF_AL + sto + t * 16) = pAl[g0 + t];
            *(uint4*)(sm + OFF_BH + sto + t * 16) = pWh[g0 + t];
            *(uint4*)(sm + OFF_BL + sto + t * 16) = pWl[g0 + t];
        }
        __syncthreads();

#pragma unroll
        for (int ks = 0; ks < 4; ks++) {
            const uint32_t kb = (uint32_t)(ks * 32);
            uint32_t ah[2][4], al[2][4];
#pragma unroll
            for (int t = 0; t < 2; t++) {
                uint32_t adr = sb + OFF_AH + (a_row + t * 16) * ROWB + kb + a_colb;
                LDSM_X4(ah[t][0], ah[t][1], ah[t][2], ah[t][3], adr);
                adr = sb + OFF_AL + (a_row + t * 16) * ROWB + kb + a_colb;
                LDSM_X4(al[t][0], al[t][1], al[t][2], al[t][3], adr);
            }
#pragma unroll
            for (int p = 0; p < 4; p++) {
                uint32_t bh[4], bl[4];
                uint32_t bdr = sb + OFF_BH + (b_row + p * 16) * ROWB + kb + b_colb;
                LDSM_X4(bh[0], bh[1], bh[2], bh[3], bdr);
                bdr = sb + OFF_BL + (b_row + p * 16) * ROWB + kb + b_colb;
                LDSM_X4(bl[0], bl[1], bl[2], bl[3], bdr);
#pragma unroll
                for (int t = 0; t < 2; t++) {
                    MMA_BF16(acc[t][p * 2 + 0], ah[t], bh[0], bh[1]);
                    MMA_BF16(acc[t][p * 2 + 0], ah[t], bl[0], bl[1]);
                    MMA_BF16(acc[t][p * 2 + 0], al[t], bh[0], bh[1]);
                    MMA_BF16(acc[t][p * 2 + 1], ah[t], bh[2], bh[3]);
                    MMA_BF16(acc[t][p * 2 + 1], ah[t], bl[2], bl[3]);
                    MMA_BF16(acc[t][p * 2 + 1], al[t], bh[2], bh[3]);
                }
            }
        }
        __syncthreads();
    }

#pragma unroll
    for (int t = 0; t < 2; t++) {
        const int mrow = m0 + wm * 32 + t * 16 + (lane >> 2);
#pragma unroll
        for (int j = 0; j < 8; j++) {
            const int n = n0 + wn * 64 + j * 8 + (lane & 3) * 2;
            float2 bv = *(const float2*)&bias[n];
            float2 v0, v1;
            v0.x = acc[t][j][0] + bv.x;
            v0.y = acc[t][j][1] + bv.y;
            v1.x = acc[t][j][2] + bv.x;
            v1.y = acc[t][j][3] + bv.y;
            if (MODE == 0) {
                *(float2*)&Y[(size_t)mrow * 1024 + n] = v0;
                *(float2*)&Y[(size_t)(mrow + 8) * 1024 + n] = v1;
            } else {
                int h = n >> 6, d = n & 63;
                int b0i = mrow >> 11, s0 = mrow & 2047;
                *(float2*)&Y[(((size_t)(b0i * H_ + h) * S_ + s0) << 6) + d] = v0;
                int b1i = (mrow + 8) >> 11, s1 = (mrow + 8) & 2047;
                *(float2*)&Y[(((size_t)(b1i * H_ + h) * S_ + s1) << 6) + d] = v1;
            }
        }
    }
}

// ===========================================================================
// Flash attention via HMMA (unchanged from round 10, passing at 499 us).
// ===========================================================================
#define A_QH 0
#define A_QL (A_QH + 128 * ROWB)        // 18432
#define A_KH (A_QL + 128 * ROWB)        // 36864
#define A_KL (A_KH + 64 * ROWB)         // 46080
#define A_VH (A_KL + 64 * ROWB)         // 55296
#define A_VL (A_VH + 64 * ROWB)         // 64512
#define ATTN_SMEM (A_VL + 64 * ROWB)    // 73728

__global__ __launch_bounds__(256)
void attn_mma(const float* __restrict__ Q, const float* __restrict__ K,
              const float* __restrict__ V, float* __restrict__ AO)
{
    extern __shared__ char sm[];
    const uint32_t sb = smem_u32(sm);
    const int tid = threadIdx.x;
    const int wid = tid >> 5;
    const int lane = tid & 31;
    const int q0 = blockIdx.x * 128;
    const int bh = blockIdx.y;

    const float* Qb = Q + (size_t)bh * (S_ * DK_);
    const float* Kb = K + (size_t)bh * (S_ * DK_);
    const float* Vb = V + (size_t)bh * (S_ * DK_);

    // Stage Q tile (scaled by 1/8, exact) as hi/lo bf16
    {
        const int lr = tid >> 1, cg = (tid & 1) * 32;
        const float* src = Qb + (size_t)(q0 + lr) * 64 + cg;
        const uint32_t sto = (uint32_t)(lr * ROWB + cg * 2);
#pragma unroll
        for (int t = 0; t < 8; t++) {
            float4 a4 = *(const float4*)(src + t * 4);
            a4.x *= 0.125f; a4.y *= 0.125f; a4.z *= 0.125f; a4.w *= 0.125f;
            float r0, r1, r2, r3;
            uint32_t h01 = pack_hi(a4.x, a4.y, r0, r1);
            uint32_t h23 = pack_hi(a4.z, a4.w, r2, r3);
            *(uint2*)(sm + A_QH + sto + t * 8) = make_uint2(h01, h23);
            *(uint2*)(sm + A_QL + sto + t * 8) =
                make_uint2(pack_lo(r0, r1), pack_lo(r2, r3));
        }
    }
    __syncthreads();

    // Per-warp persistent Q fragments (4 k-steps over d=64)
    const int wr0 = wid * 16;
    uint32_t qh[4][4], ql[4][4];
    {
        const uint32_t base =
            sb + A_QH + (uint32_t)(wr0 + (lane & 15)) * ROWB + (lane >> 4) * 16;
#pragma unroll
        for (int t = 0; t < 4; t++) {
            LDSM_X4(qh[t][0], qh[t][1], qh[t][2], qh[t][3], base + t * 32);
            LDSM_X4(ql[t][0], ql[t][1], ql[t][2], ql[t][3],
                    base + (A_QL - A_QH) + t * 32);
        }
    }

    float m0 = -1e30f, m1 = -1e30f, l0 = 0.0f, l1 = 0.0f;
    float oc[8][4];
#pragma unroll
    for (int n = 0; n < 8; n++)
#pragma unroll
        for (int c = 0; c < 4; c++) oc[n][c] = 0.0f;

    const uint32_t b_row = (uint32_t)((lane & 7) + ((lane >> 4) & 1) * 8);
    const uint32_t b_colb = (uint32_t)(((lane >> 3) & 1) * 16);
    const int row0 = q0 + wr0 + (lane >> 2);

    const int nkt = (q0 >> 6) + 2;     // kv tiles covering cols 0..q0+127
    for (int kt = 0; kt < nkt; kt++) {
        const int kv0 = kt * 64;

        // Load K tile [64 j][64 d] hi/lo
        {
            const int lr = tid >> 2, cg = (tid & 3) * 16;
            const float* src = Kb + (size_t)(kv0 + lr) * 64 + cg;
            const uint32_t sto = (uint32_t)(lr * ROWB + cg * 2);
#pragma unroll
            for (int t = 0; t < 4; t++) {
                float4 a4 = *(const float4*)(src + t * 4);
                float r0, r1, r2, r3;
                uint32_t h01 = pack_hi(a4.x, a4.y, r0, r1);
                uint32_t h23 = pack_hi(a4.z, a4.w, r2, r3);
                *(uint2*)(sm + A_KH + sto + t * 8) = make_uint2(h01, h23);
                *(uint2*)(sm + A_KL + sto + t * 8) =
                    make_uint2(pack_lo(r0, r1), pack_lo(r2, r3));
            }
        }
        // Load V tile transposed: Vt[d][j] hi/lo
        {
            const int j = tid & 63, d0 = (tid >> 6) * 16;
            const float* src = Vb + (size_t)(kv0 + j) * 64 + d0;
#pragma unroll
            for (int i = 0; i < 4; i++) {
                float4 v4 = *(const float4*)(src + i * 4);
                float vv[4] = {v4.x, v4.y, v4.z, v4.w};
#pragma unroll
                for (int e = 0; e < 4; e++) {
                    const int d = d0 + i * 4 + e;
                    __nv_bfloat16 hh = __float2bfloat16(vv[e]);
                    float rr = vv[e] - __bfloat162float(hh);
                    *(__nv_bfloat16*)(sm + A_VH + d * ROWB + j * 2) = hh;
                    *(__nv_bfloat16*)(sm + A_VL + d * ROWB + j * 2) =
                        __float2bfloat16(rr);
                }
            }
        }
        __syncthreads();

        if (kv0 <= q0 + wr0 + 15) {     // warp has at least one unmasked element
            // S = Q K^T (3-term split)
            float sc[8][4];
#pragma unroll
            for (int n = 0; n < 8; n++)
#pragma unroll
                for (int c = 0; c < 4; c++) sc[n][c] = 0.0f;

#pragma unroll
            for (int t = 0; t < 4; t++) {
#pragma unroll
                for (int pp = 0; pp < 4; pp++) {
                    uint32_t kb0, kb1, kb2, kb3, kl0, kl1, kl2, kl3;
                    uint32_t adr =
                        sb + A_KH + (pp * 16 + b_row) * ROWB + t * 32 + b_colb;
                    LDSM_X4(kb0, kb1, kb2, kb3, adr);
                    LDSM_X4(kl0, kl1, kl2, kl3, adr + (A_KL - A_KH));
                    MMA_BF16(sc[pp * 2 + 0], qh[t], kb0, kb1);
                    MMA_BF16(sc[pp * 2 + 0], qh[t], kl0, kl1);
                    MMA_BF16(sc[pp * 2 + 0], ql[t], kb0, kb1);
                    MMA_BF16(sc[pp * 2 + 1], qh[t], kb2, kb3);
                    MMA_BF16(sc[pp * 2 + 1], qh[t], kl2, kl3);
                    MMA_BF16(sc[pp * 2 + 1], ql[t], kb2, kb3);
                }
            }

            // Causal mask on diagonal-overlapping tiles
            if (kv0 + 63 > q0 + wr0) {
#pragma unroll
                for (int n = 0; n < 8; n++) {
                    const int col = kv0 + n * 8 + (lane & 3) * 2;
                    if (col > row0)         sc[n][0] = -1e30f;
                    if (col + 1 > row0)     sc[n][1] = -1e30f;
                    if (col > row0 + 8)     sc[n][2] = -1e30f;
                    if (col + 1 > row0 + 8) sc[n][3] = -1e30f;
                }
            }

            // Online softmax (rows live in 4-lane groups)
            float mx0 = -1e30f, mx1 = -1e30f;
#pragma unroll
            for (int n = 0; n < 8; n++) {
                mx0 = fmaxf(mx0, fmaxf(sc[n][0], sc[n][1]));
                mx1 = fmaxf(mx1, fmaxf(sc[n][2], sc[n][3]));
            }
            mx0 = fmaxf(mx0, __shfl_xor_sync(0xffffffffu, mx0, 1));
            mx0 = fmaxf(mx0, __shfl_xor_sync(0xffffffffu, mx0, 2));
            mx1 = fmaxf(mx1, __shfl_xor_sync(0xffffffffu, mx1, 1));
            mx1 = fmaxf(mx1, __shfl_xor_sync(0xffffffffu, mx1, 2));

            const float mn0 = fmaxf(m0, mx0), mn1 = fmaxf(m1, mx1);
            const float corr0 = __expf(m0 - mn0), corr1 = __expf(m1 - mn1);
            float rs0 = 0.0f, rs1 = 0.0f;
#pragma unroll
            for (int n = 0; n < 8; n++) {
                sc[n][0] = __expf(sc[n][0] - mn0);
                sc[n][1] = __expf(sc[n][1] - mn0);
                sc[n][2] = __expf(sc[n][2] - mn1);
                sc[n][3] = __expf(sc[n][3] - mn1);
                rs0 += sc[n][0] + sc[n][1];
                rs1 += sc[n][2] + sc[n][3];
            }
            rs0 += __shfl_xor_sync(0xffffffffu, rs0, 1);
            rs0 += __shfl_xor_sync(0xffffffffu, rs0, 2);
            rs1 += __shfl_xor_sync(0xffffffffu, rs1, 1);
            rs1 += __shfl_xor_sync(0xffffffffu, rs1, 2);
            l0 = l0 * corr0 + rs0;  m0 = mn0;
            l1 = l1 * corr1 + rs1;  m1 = mn1;
#pragma unroll
            for (int n = 0; n < 8; n++) {
                oc[n][0] *= corr0;  oc[n][1] *= corr0;
                oc[n][2] *= corr1;  oc[n][3] *= corr1;
            }

            // O += P V  (P hi/lo from S fragments; V from transposed smem)
#pragma unroll
            for (int t = 0; t < 4; t++) {
                uint32_t ph[4], pl[4];
                float ra, rb;
                ph[0] = pack_hi(sc[2 * t][0], sc[2 * t][1], ra, rb);
                pl[0] = pack_lo(ra, rb);
                ph[1] = pack_hi(sc[2 * t][2], sc[2 * t][3], ra, rb);
                pl[1] = pack_lo(ra, rb);
                ph[2] = pack_hi(sc[2 * t + 1][0], sc[2 * t + 1][1], ra, rb);
                pl[2] = pack_lo(ra, rb);
                ph[3] = pack_hi(sc[2 * t + 1][2], sc[2 * t + 1][3], ra, rb);
                pl[3] = pack_lo(ra, rb);
#pragma unroll
                for (int pp = 0; pp < 4; pp++) {
                    uint32_t vh0, vh1, vh2, vh3, vl0, vl1, vl2, vl3;
                    uint32_t adr =
                        sb + A_VH + (pp * 16 + b_row) * ROWB + t * 32 + b_colb;
                    LDSM_X4(vh0, vh1, vh2, vh3, adr);
                    LDSM_X4(vl0, vl1, vl2, vl3, adr + (A_VL - A_VH));
                    MMA_BF16(oc[pp * 2 + 0], ph, vh0, vh1);
                    MMA_BF16(oc[pp * 2 + 0], ph, vl0, vl1);
                    MMA_BF16(oc[pp * 2 + 0], pl, vh0, vh1);
                    MMA_BF16(oc[pp * 2 + 1], ph, vh2, vh3);
                    MMA_BF16(oc[pp * 2 + 1], ph, vl2, vl3);
                    MMA_BF16(oc[pp * 2 + 1], pl, vh2, vh3);
                }
            }
        }
        __syncthreads();
    }

    // Epilogue: normalize + write to [B,S,1024] at this head's column block
    const int b = bh >> 4, h = bh & 15;
    const float inv0 = 1.0f / l0, inv1 = 1.0f / l1;
#pragma unroll
    for (int n = 0; n < 8; n++) {
        const int d = h * 64 + n * 8 + (lane & 3) * 2;
        float2 v0 = make_float2(oc[n][0] * inv0, oc[n][1] * inv0);
        float2 v1 = make_float2(oc[n][2] * inv1, oc[n][3] * inv1);
        *(float2*)&AO[(size_t)(b * S_ + row0) * DM_ + d] = v0;
        *(float2*)&AO[(size_t)(b * S_ + row0 + 8) * DM_ + d] = v1;
    }
}

// ---------------------------------------------------------------------------
extern "C" void kernel_launch(void* const* d_in, const int* in_sizes, int n_in,
                              void* d_out, int out_size)
{
    const float* q  = (const float*)d_in[0];
    const float* k  = (const float*)d_in[1];
    const float* v  = (const float*)d_in[2];
    // d_in[3] = mask (deterministic causal tril; handled structurally)
    const float* wq = (const float*)d_in[4];
    const float* bq = (const float*)d_in[5];
    const float* wk = (const float*)d_in[6];
    const float* bk = (const float*)d_in[7];
    const float* wv = (const float*)d_in[8];
    const float* bv = (const float*)d_in[9];
    const float* wo = (const float*)d_in[10];
    const float* bo = (const float*)d_in[11];
    float* out = (float*)d_out;

    float *pQ, *pK, *pV, *pA;
    __nv_bfloat16 *pXh, *pXl, *pWh, *pWl;
    cudaGetSymbolAddress((void**)&pQ, g_Q);
    cudaGetSymbolAddress((void**)&pK, g_K);
    cudaGetSymbolAddress((void**)&pV, g_V);
    cudaGetSymbolAddress((void**)&pA, g_AO);
    cudaGetSymbolAddress((void**)&pXh, g_Xh);
    cudaGetSymbolAddress((void**)&pXl, g_Xl);
    cudaGetSymbolAddress((void**)&pWh, g_Wh);
    cudaGetSymbolAddress((void**)&pWl, g_Wl);

    static bool attr_done = false;
    if (!attr_done) {
        cudaFuncSetAttribute(gemm_mma<0>, cudaFuncAttributeMaxDynamicSharedMemorySize,
                             GEMM_SMEM);
        cudaFuncSetAttribute(gemm_mma<1>, cudaFuncAttributeMaxDynamicSharedMemorySize,
                             GEMM_SMEM);
        cudaFuncSetAttribute(attn_mma, cudaFuncAttributeMaxDynamicSharedMemorySize,
                             ATTN_SMEM);
        attr_done = true;
    }

    const int nX4 = M_ * DM_ / 4;      // 2097152
    const int nW4 = DM_ * DM_ / 4;     // 262144
    dim3 gg(DM_ / 128, M_ / 128);      // (8, 64)

    // Q projection
    split_k<<<(nX4 + 255) / 256, 256>>>(q, pXh, pXl, nX4);
    split_k<<<(nW4 + 255) / 256, 256>>>(wq, pWh, pWl, nW4);
    gemm_mma<1><<<gg, 256, GEMM_SMEM>>>(pXh, pXl, pWh, pWl, bq, pQ);
    // K projection
    split_k<<<(nX4 + 255) / 256, 256>>>(k, pXh, pXl, nX4);
    split_k<<<(nW4 + 255) / 256, 256>>>(wk, pWh, pWl, nW4);
    gemm_mma<1><<<gg, 256, GEMM_SMEM>>>(pXh, pXl, pWh, pWl, bk, pK);
    // V projection
    split_k<<<(nX4 + 255) / 256, 256>>>(v, pXh, pXl, nX4);
    split_k<<<(nW4 + 255) / 256, 256>>>(wv, pWh, pWl, nW4);
    gemm_mma<1><<<gg, 256, GEMM_SMEM>>>(pXh, pXl, pWh, pWl, bv, pV);

    attn_mma<<<dim3(S_ / 128, B_ * H_), 256, ATTN_SMEM>>>(pQ, pK, pV, pA);

    // Output projection
    split_k<<<(nX4 + 255) / 256, 256>>>(pA, pXh, pXl, nX4);
    split_k<<<(nW4 + 255) / 256, 256>>>(wo, pWh, pWl, nW4);
    gemm_mma<0><<<gg, 256, GEMM_SMEM>>>(pXh, pXl, pWh, pWl, bo, out);
}

// round 13
// speedup vs baseline: 2.5793x; 1.1112x over previous
#include <cuda_runtime.h>
#include <cuda_bf16.h>
#include <cstdint>

// Problem constants
#define B_  4
#define S_  2048
#define H_  16
#define DK_ 64
#define DM_ 1024
#define M_  (B_ * S_)   // 8192 rows for projections

// Scratch (device globals: allocation-free per harness rules)
__device__ float g_Q[(size_t)B_ * H_ * S_ * DK_];   // [B,H,S,dk]
__device__ float g_K[(size_t)B_ * H_ * S_ * DK_];
__device__ float g_V[(size_t)B_ * H_ * S_ * DK_];
__device__ float g_AO[(size_t)B_ * S_ * DM_];       // [B,S,D]
// bf16 hi/lo staging for GEMM operands (reused across the 4 sequential GEMMs)
__device__ __nv_bfloat16 g_Xh[(size_t)M_ * DM_];
__device__ __nv_bfloat16 g_Xl[(size_t)M_ * DM_];
__device__ __nv_bfloat16 g_Wh[(size_t)DM_ * DM_];
__device__ __nv_bfloat16 g_Wl[(size_t)DM_ * DM_];

// ===========================================================================
// helpers
// ===========================================================================
__device__ __forceinline__ uint32_t smem_u32(const void* p) {
    uint32_t a;
    asm("{ .reg .u64 t; cvta.to.shared.u64 t, %1; cvt.u32.u64 %0, t; }"
        : "=r"(a) : "l"(p));
    return a;
}

#define LDSM_X4(r0, r1, r2, r3, addr)                                        \
    asm volatile("ldmatrix.sync.aligned.m8n8.x4.shared.b16 {%0,%1,%2,%3}, [%4];" \
                 : "=r"(r0), "=r"(r1), "=r"(r2), "=r"(r3) : "r"(addr))

#define MMA_BF16(d, a, B0, B1)                                               \
    asm volatile("mma.sync.aligned.m16n8k16.row.col.f32.bf16.bf16.f32 "      \
                 "{%0,%1,%2,%3}, {%4,%5,%6,%7}, {%8,%9}, {%0,%1,%2,%3};"     \
                 : "+f"((d)[0]), "+f"((d)[1]), "+f"((d)[2]), "+f"((d)[3])    \
                 : "r"((a)[0]), "r"((a)[1]), "r"((a)[2]), "r"((a)[3]),       \
                   "r"(B0), "r"(B1))

#define CP_ASYNC16(dst, src)                                                 \
    asm volatile("cp.async.cg.shared.global [%0], [%1], 16;"                 \
                 :: "r"(dst), "l"(src) : "memory")
#define CP_COMMIT() asm volatile("cp.async.commit_group;" ::: "memory")
#define CP_WAIT1()  asm volatile("cp.async.wait_group 1;" ::: "memory")
#define CP_WAIT0()  asm volatile("cp.async.wait_group 0;" ::: "memory")

// bf16 hi/lo split helpers
__device__ __forceinline__ uint32_t pack_hi(float a, float b, float& ra, float& rb) {
    __nv_bfloat16 ha = __float2bfloat16(a);
    __nv_bfloat16 hb = __float2bfloat16(b);
    ra = a - __bfloat162float(ha);
    rb = b - __bfloat162float(hb);
    __nv_bfloat162 p;
    p.x = ha; p.y = hb;
    return *(uint32_t*)&p;
}
__device__ __forceinline__ uint32_t pack_lo(float ra, float rb) {
    __nv_bfloat162 p;
    p.x = __float2bfloat16(ra);
    p.y = __float2bfloat16(rb);
    return *(uint32_t*)&p;
}

// ===========================================================================
// split_k: fp32 -> bf16 hi/lo arrays (memory-bound pre-pass).
// ===========================================================================
__global__ __launch_bounds__(256)
void split_k(const float* __restrict__ src, __nv_bfloat16* __restrict__ hi,
             __nv_bfloat16* __restrict__ lo, int n4)
{
    int i = blockIdx.x * blockDim.x + threadIdx.x;
    if (i < n4) {
        float4 v = ((const float4*)src)[i];
        float r0, r1, r2, r3;
        uint32_t h01 = pack_hi(v.x, v.y, r0, r1);
        uint32_t h23 = pack_hi(v.z, v.w, r2, r3);
        ((uint2*)hi)[i] = make_uint2(h01, h23);
        ((uint2*)lo)[i] = make_uint2(pack_lo(r0, r1), pack_lo(r2, r3));
    }
}

// ===========================================================================
// HMMA GEMM on pre-split bf16 operands, cp.async double-buffered pipeline.
// Y = X @ W^T + bias. Block tile 128x128, K-chunk 32 (32 chunks),
// 8 warps (4M x 2N), warp tile 32x64. Two 40KB smem buffers -> occ 2.
// MODE 0: Y[m*1024+n].  MODE 1: head-split [B,H,S,64].
// ===========================================================================
#define ROWB2   80                      // 64B data + 16B pad per row
#define T_AH    0
#define T_AL    (T_AH + 128 * ROWB2)    // 10240
#define T_WH    (T_AL + 128 * ROWB2)    // 20480
#define T_WL    (T_WH + 128 * ROWB2)    // 30720
#define BUF_SZ  (T_WL + 128 * ROWB2)    // 40960
#define GEMM_SMEM (2 * BUF_SZ)          // 81920

template <int MODE>
__global__ __launch_bounds__(256, 2)
void gemm_mma(const __nv_bfloat16* __restrict__ Ah,
              const __nv_bfloat16* __restrict__ Al,
              const __nv_bfloat16* __restrict__ Wh,
              const __nv_bfloat16* __restrict__ Wl,
              const float* __restrict__ bias, float* __restrict__ Y)
{
    extern __shared__ char sm[];
    const uint32_t sb = smem_u32(sm);
    const int tid = threadIdx.x;
    const int wid = tid >> 5;
    const int lane = tid & 31;
    const int wm = wid & 3;             // 0..3  (M)
    const int wn = wid >> 2;            // 0..1  (N)
    const int m0 = blockIdx.y * 128;
    const int n0 = blockIdx.x * 128;

    // Staging mapping: row = tid>>1 (0..127), half = tid&1 (32B halves of 64B)
    const int lr = tid >> 1;
    const int half = tid & 1;
    const char* gAh = (const char*)(Ah + (size_t)(m0 + lr) * 1024) + half * 32;
    const char* gAl = (const char*)(Al + (size_t)(m0 + lr) * 1024) + half * 32;
    const char* gWh = (const char*)(Wh + (size_t)(n0 + lr) * 1024) + half * 32;
    const char* gWl = (const char*)(Wl + (size_t)(n0 + lr) * 1024) + half * 32;
    const uint32_t srow = (uint32_t)(lr * ROWB2 + half * 32);

    float acc[2][8][4];
#pragma unroll
    for (int t = 0; t < 2; t++)
#pragma unroll
        for (int j = 0; j < 8; j++)
#pragma unroll
            for (int c = 0; c < 4; c++) acc[t][j][c] = 0.0f;

    const uint32_t a_row = (uint32_t)(wm * 32 + (lane & 15));
    const uint32_t a_colb = (uint32_t)((lane >> 4) * 16);
    const uint32_t b_row = (uint32_t)(wn * 64 + (lane & 7) + ((lane >> 4) & 1) * 8);
    const uint32_t b_colb = (uint32_t)(((lane >> 3) & 1) * 16);

#define GEMM_ISSUE(kc, buf) do {                                             \
    const uint32_t _d = sb + (buf) * BUF_SZ + srow;                          \
    const int _g = (kc) * 64;                                                \
    CP_ASYNC16(_d + T_AH,      gAh + _g);                                    \
    CP_ASYNC16(_d + T_AH + 16, gAh + _g + 16);                               \
    CP_ASYNC16(_d + T_AL,      gAl + _g);                                    \
    CP_ASYNC16(_d + T_AL + 16, gAl + _g + 16);                               \
    CP_ASYNC16(_d + T_WH,      gWh + _g);                                    \
    CP_ASYNC16(_d + T_WH + 16, gWh + _g + 16);                               \
    CP_ASYNC16(_d + T_WL,      gWl + _g);                                    \
    CP_ASYNC16(_d + T_WL + 16, gWl + _g + 16);                               \
} while (0)

    GEMM_ISSUE(0, 0);
    CP_COMMIT();

    const int NC = 32;
    for (int kc = 0; kc < NC; kc++) {
        const int buf = kc & 1;
        if (kc + 1 < NC) {
            GEMM_ISSUE(kc + 1, buf ^ 1);
            CP_COMMIT();
            CP_WAIT1();
        } else {
            CP_WAIT0();
        }
        __syncthreads();               // chunk kc visible to all threads

        const uint32_t bb = sb + buf * BUF_SZ;
#pragma unroll
        for (int ks = 0; ks < 2; ks++) {
            const uint32_t kb = (uint32_t)(ks * 32);
            uint32_t ah[2][4], al[2][4];
#pragma unroll
            for (int t = 0; t < 2; t++) {
                uint32_t adr = bb + T_AH + (a_row + t * 16) * ROWB2 + kb + a_colb;
                LDSM_X4(ah[t][0], ah[t][1], ah[t][2], ah[t][3], adr);
                adr = bb + T_AL + (a_row + t * 16) * ROWB2 + kb + a_colb;
                LDSM_X4(al[t][0], al[t][1], al[t][2], al[t][3], adr);
            }
#pragma unroll
            for (int p = 0; p < 4; p++) {
                uint32_t bh[4], bl[4];
                uint32_t bdr = bb + T_WH + (b_row + p * 16) * ROWB2 + kb + b_colb;
                LDSM_X4(bh[0], bh[1], bh[2], bh[3], bdr);
                bdr = bb + T_WL + (b_row + p * 16) * ROWB2 + kb + b_colb;
                LDSM_X4(bl[0], bl[1], bl[2], bl[3], bdr);
#pragma unroll
                for (int t = 0; t < 2; t++) {
                    MMA_BF16(acc[t][p * 2 + 0], ah[t], bh[0], bh[1]);
                    MMA_BF16(acc[t][p * 2 + 0], ah[t], bl[0], bl[1]);
                    MMA_BF16(acc[t][p * 2 + 0], al[t], bh[0], bh[1]);
                    MMA_BF16(acc[t][p * 2 + 1], ah[t], bh[2], bh[3]);
                    MMA_BF16(acc[t][p * 2 + 1], ah[t], bl[2], bl[3]);
                    MMA_BF16(acc[t][p * 2 + 1], al[t], bh[2], bh[3]);
                }
            }
        }
        __syncthreads();               // done reading buf before it refills
    }
#undef GEMM_ISSUE

#pragma unroll
    for (int t = 0; t < 2; t++) {
        const int mrow = m0 + wm * 32 + t * 16 + (lane >> 2);
#pragma unroll
        for (int j = 0; j < 8; j++) {
            const int n = n0 + wn * 64 + j * 8 + (lane & 3) * 2;
            float2 bv = *(const float2*)&bias[n];
            float2 v0, v1;
            v0.x = acc[t][j][0] + bv.x;
            v0.y = acc[t][j][1] + bv.y;
            v1.x = acc[t][j][2] + bv.x;
            v1.y = acc[t][j][3] + bv.y;
            if (MODE == 0) {
                *(float2*)&Y[(size_t)mrow * 1024 + n] = v0;
                *(float2*)&Y[(size_t)(mrow + 8) * 1024 + n] = v1;
            } else {
                int h = n >> 6, d = n & 63;
                int b0i = mrow >> 11, s0 = mrow & 2047;
                *(float2*)&Y[(((size_t)(b0i * H_ + h) * S_ + s0) << 6) + d] = v0;
                int b1i = (mrow + 8) >> 11, s1 = (mrow + 8) & 2047;
                *(float2*)&Y[(((size_t)(b1i * H_ + h) * S_ + s1) << 6) + d] = v1;
            }
        }
    }
}

// ===========================================================================
// Flash attention via HMMA (R10 structure; launch_bounds(256,2) for occ 2).
// ===========================================================================
#define ROWB 144
#define A_QH 0
#define A_QL (A_QH + 128 * ROWB)        // 18432
#define A_KH (A_QL + 128 * ROWB)        // 36864
#define A_KL (A_KH + 64 * ROWB)         // 46080
#define A_VH (A_KL + 64 * ROWB)         // 55296
#define A_VL (A_VH + 64 * ROWB)         // 64512
#define ATTN_SMEM (A_VL + 64 * ROWB)    // 73728

__global__ __launch_bounds__(256, 2)
void attn_mma(const float* __restrict__ Q, const float* __restrict__ K,
              const float* __restrict__ V, float* __restrict__ AO)
{
    extern __shared__ char sm[];
    const uint32_t sb = smem_u32(sm);
    const int tid = threadIdx.x;
    const int wid = tid >> 5;
    const int lane = tid & 31;
    const int q0 = blockIdx.x * 128;
    const int bh = blockIdx.y;

    const float* Qb = Q + (size_t)bh * (S_ * DK_);
    const float* Kb = K + (size_t)bh * (S_ * DK_);
    const float* Vb = V + (size_t)bh * (S_ * DK_);

    // Stage Q tile (scaled by 1/8, exact) as hi/lo bf16
    {
        const int lr = tid >> 1, cg = (tid & 1) * 32;
        const float* src = Qb + (size_t)(q0 + lr) * 64 + cg;
        const uint32_t sto = (uint32_t)(lr * ROWB + cg * 2);
#pragma unroll
        for (int t = 0; t < 8; t++) {
            float4 a4 = *(const float4*)(src + t * 4);
            a4.x *= 0.125f; a4.y *= 0.125f; a4.z *= 0.125f; a4.w *= 0.125f;
            float r0, r1, r2, r3;
            uint32_t h01 = pack_hi(a4.x, a4.y, r0, r1);
            uint32_t h23 = pack_hi(a4.z, a4.w, r2, r3);
            *(uint2*)(sm + A_QH + sto + t * 8) = make_uint2(h01, h23);
            *(uint2*)(sm + A_QL + sto + t * 8) =
                make_uint2(pack_lo(r0, r1), pack_lo(r2, r3));
        }
    }
    __syncthreads();

    // Per-warp persistent Q fragments (4 k-steps over d=64)
    const int wr0 = wid * 16;
    uint32_t qh[4][4], ql[4][4];
    {
        const uint32_t base =
            sb + A_QH + (uint32_t)(wr0 + (lane & 15)) * ROWB + (lane >> 4) * 16;
#pragma unroll
        for (int t = 0; t < 4; t++) {
            LDSM_X4(qh[t][0], qh[t][1], qh[t][2], qh[t][3], base + t * 32);
            LDSM_X4(ql[t][0], ql[t][1], ql[t][2], ql[t][3],
                    base + (A_QL - A_QH) + t * 32);
        }
    }

    float m0 = -1e30f, m1 = -1e30f, l0 = 0.0f, l1 = 0.0f;
    float oc[8][4];
#pragma unroll
    for (int n = 0; n < 8; n++)
#pragma unroll
        for (int c = 0; c < 4; c++) oc[n][c] = 0.0f;

    const uint32_t b_row = (uint32_t)((lane & 7) + ((lane >> 4) & 1) * 8);
    const uint32_t b_colb = (uint32_t)(((lane >> 3) & 1) * 16);
    const int row0 = q0 + wr0 + (lane >> 2);

    const int nkt = (q0 >> 6) + 2;     // kv tiles covering cols 0..q0+127
    for (int kt = 0; kt < nkt; kt++) {
        const int kv0 = kt * 64;

        // Load K tile [64 j][64 d] hi/lo
        {
            const int lr = tid >> 2, cg = (tid & 3) * 16;
            const float* src = Kb + (size_t)(kv0 + lr) * 64 + cg;
            const uint32_t sto = (uint32_t)(lr * ROWB + cg * 2);
#pragma unroll
            for (int t = 0; t < 4; t++) {
                float4 a4 = *(const float4*)(src + t * 4);
                float r0, r1, r2, r3;
                uint32_t h01 = pack_hi(a4.x, a4.y, r0, r1);
                uint32_t h23 = pack_hi(a4.z, a4.w, r2, r3);
                *(uint2*)(sm + A_KH + sto + t * 8) = make_uint2(h01, h23);
                *(uint2*)(sm + A_KL + sto + t * 8) =
                    make_uint2(pack_lo(r0, r1), pack_lo(r2, r3));
            }
        }
        // Load V tile transposed: Vt[d][j] hi/lo
        {
            const int j = tid & 63, d0 = (tid >> 6) * 16;
            const float* src = Vb + (size_t)(kv0 + j) * 64 + d0;
#pragma unroll
            for (int i = 0; i < 4; i++) {
                float4 v4 = *(const float4*)(src + i * 4);
                float vv[4] = {v4.x, v4.y, v4.z, v4.w};
#pragma unroll
                for (int e = 0; e < 4; e++) {
                    const int d = d0 + i * 4 + e;
                    __nv_bfloat16 hh = __float2bfloat16(vv[e]);
                    float rr = vv[e] - __bfloat162float(hh);
                    *(__nv_bfloat16*)(sm + A_VH + d * ROWB + j * 2) = hh;
                    *(__nv_bfloat16*)(sm + A_VL + d * ROWB + j * 2) =
                        __float2bfloat16(rr);
                }
            }
        }
        __syncthreads();

        if (kv0 <= q0 + wr0 + 15) {     // warp has at least one unmasked element
            // S = Q K^T (3-term split)
            float sc[8][4];
#pragma unroll
            for (int n = 0; n < 8; n++)
#pragma unroll
                for (int c = 0; c < 4; c++) sc[n][c] = 0.0f;

#pragma unroll
            for (int t = 0; t < 4; t++) {
#pragma unroll
                for (int pp = 0; pp < 4; pp++) {
                    uint32_t kb0, kb1, kb2, kb3, kl0, kl1, kl2, kl3;
                    uint32_t adr =
                        sb + A_KH + (pp * 16 + b_row) * ROWB + t * 32 + b_colb;
                    LDSM_X4(kb0, kb1, kb2, kb3, adr);
                    LDSM_X4(kl0, kl1, kl2, kl3, adr + (A_KL - A_KH));
                    MMA_BF16(sc[pp * 2 + 0], qh[t], kb0, kb1);
                    MMA_BF16(sc[pp * 2 + 0], qh[t], kl0, kl1);
                    MMA_BF16(sc[pp * 2 + 0], ql[t], kb0, kb1);
                    MMA_BF16(sc[pp * 2 + 1], qh[t], kb2, kb3);
                    MMA_BF16(sc[pp * 2 + 1], qh[t], kl2, kl3);
                    MMA_BF16(sc[pp * 2 + 1], ql[t], kb2, kb3);
                }
            }

            // Causal mask on diagonal-overlapping tiles
            if (kv0 + 63 > q0 + wr0) {
#pragma unroll
                for (int n = 0; n < 8; n++) {
                    const int col = kv0 + n * 8 + (lane & 3) * 2;
                    if (col > row0)         sc[n][0] = -1e30f;
                    if (col + 1 > row0)     sc[n][1] = -1e30f;
                    if (col > row0 + 8)     sc[n][2] = -1e30f;
                    if (col + 1 > row0 + 8) sc[n][3] = -1e30f;
                }
            }

            // Online softmax (rows live in 4-lane groups)
            float mx0 = -1e30f, mx1 = -1e30f;
#pragma unroll
            for (int n = 0; n < 8; n++) {
                mx0 = fmaxf(mx0, fmaxf(sc[n][0], sc[n][1]));
                mx1 = fmaxf(mx1, fmaxf(sc[n][2], sc[n][3]));
            }
            mx0 = fmaxf(mx0, __shfl_xor_sync(0xffffffffu, mx0, 1));
            mx0 = fmaxf(mx0, __shfl_xor_sync(0xffffffffu, mx0, 2));
            mx1 = fmaxf(mx1, __shfl_xor_sync(0xffffffffu, mx1, 1));
            mx1 = fmaxf(mx1, __shfl_xor_sync(0xffffffffu, mx1, 2));

            const float mn0 = fmaxf(m0, mx0), mn1 = fmaxf(m1, mx1);
            const float corr0 = __expf(m0 - mn0), corr1 = __expf(m1 - mn1);
            float rs0 = 0.0f, rs1 = 0.0f;
#pragma unroll
            for (int n = 0; n < 8; n++) {
                sc[n][0] = __expf(sc[n][0] - mn0);
                sc[n][1] = __expf(sc[n][1] - mn0);
                sc[n][2] = __expf(sc[n][2] - mn1);
                sc[n][3] = __expf(sc[n][3] - mn1);
                rs0 += sc[n][0] + sc[n][1];
                rs1 += sc[n][2] + sc[n][3];
            }
            rs0 += __shfl_xor_sync(0xffffffffu, rs0, 1);
            rs0 += __shfl_xor_sync(0xffffffffu, rs0, 2);
            rs1 += __shfl_xor_sync(0xffffffffu, rs1, 1);
            rs1 += __shfl_xor_sync(0xffffffffu, rs1, 2);
            l0 = l0 * corr0 + rs0;  m0 = mn0;
            l1 = l1 * corr1 + rs1;  m1 = mn1;
#pragma unroll
            for (int n = 0; n < 8; n++) {
                oc[n][0] *= corr0;  oc[n][1] *= corr0;
                oc[n][2] *= corr1;  oc[n][3] *= corr1;
            }

            // O += P V  (P hi/lo from S fragments; V from transposed smem)
#pragma unroll
            for (int t = 0; t < 4; t++) {
                uint32_t ph[4], pl[4];
                float ra, rb;
                ph[0] = pack_hi(sc[2 * t][0], sc[2 * t][1], ra, rb);
                pl[0] = pack_lo(ra, rb);
                ph[1] = pack_hi(sc[2 * t][2], sc[2 * t][3], ra, rb);
                pl[1] = pack_lo(ra, rb);
                ph[2] = pack_hi(sc[2 * t + 1][0], sc[2 * t + 1][1], ra, rb);
                pl[2] = pack_lo(ra, rb);
                ph[3] = pack_hi(sc[2 * t + 1][2], sc[2 * t + 1][3], ra, rb);
                pl[3] = pack_lo(ra, rb);
#pragma unroll
                for (int pp = 0; pp < 4; pp++) {
                    uint32_t vh0, vh1, vh2, vh3, vl0, vl1, vl2, vl3;
                    uint32_t adr =
                        sb + A_VH + (pp * 16 + b_row) * ROWB + t * 32 + b_colb;
                    LDSM_X4(vh0, vh1, vh2, vh3, adr);
                    LDSM_X4(vl0, vl1, vl2, vl3, adr + (A_VL - A_VH));
                    MMA_BF16(oc[pp * 2 + 0], ph, vh0, vh1);
                    MMA_BF16(oc[pp * 2 + 0], ph, vl0, vl1);
                    MMA_BF16(oc[pp * 2 + 0], pl, vh0, vh1);
                    MMA_BF16(oc[pp * 2 + 1], ph, vh2, vh3);
                    MMA_BF16(oc[pp * 2 + 1], ph, vl2, vl3);
                    MMA_BF16(oc[pp * 2 + 1], pl, vh2, vh3);
                }
            }
        }
        __syncthreads();
    }

    // Epilogue: normalize + write to [B,S,1024] at this head's column block
    const int b = bh >> 4, h = bh & 15;
    const float inv0 = 1.0f / l0, inv1 = 1.0f / l1;
#pragma unroll
    for (int n = 0; n < 8; n++) {
        const int d = h * 64 + n * 8 + (lane & 3) * 2;
        float2 v0 = make_float2(oc[n][0] * inv0, oc[n][1] * inv0);
        float2 v1 = make_float2(oc[n][2] * inv1, oc[n][3] * inv1);
        *(float2*)&AO[(size_t)(b * S_ + row0) * DM_ + d] = v0;
        *(float2*)&AO[(size_t)(b * S_ + row0 + 8) * DM_ + d] = v1;
    }
}

// ---------------------------------------------------------------------------
extern "C" void kernel_launch(void* const* d_in, const int* in_sizes, int n_in,
                              void* d_out, int out_size)
{
    const float* q  = (const float*)d_in[0];
    const float* k  = (const float*)d_in[1];
    const float* v  = (const float*)d_in[2];
    // d_in[3] = mask (deterministic causal tril; handled structurally)
    const float* wq = (const float*)d_in[4];
    const float* bq = (const float*)d_in[5];
    const float* wk = (const float*)d_in[6];
    const float* bk = (const float*)d_in[7];
    const float* wv = (const float*)d_in[8];
    const float* bv = (const float*)d_in[9];
    const float* wo = (const float*)d_in[10];
    const float* bo = (const float*)d_in[11];
    float* out = (float*)d_out;

    float *pQ, *pK, *pV, *pA;
    __nv_bfloat16 *pXh, *pXl, *pWh, *pWl;
    cudaGetSymbolAddress((void**)&pQ, g_Q);
    cudaGetSymbolAddress((void**)&pK, g_K);
    cudaGetSymbolAddress((void**)&pV, g_V);
    cudaGetSymbolAddress((void**)&pA, g_AO);
    cudaGetSymbolAddress((void**)&pXh, g_Xh);
    cudaGetSymbolAddress((void**)&pXl, g_Xl);
    cudaGetSymbolAddress((void**)&pWh, g_Wh);
    cudaGetSymbolAddress((void**)&pWl, g_Wl);

    static bool attr_done = false;
    if (!attr_done) {
        cudaFuncSetAttribute(gemm_mma<0>, cudaFuncAttributeMaxDynamicSharedMemorySize,
                             GEMM_SMEM);
        cudaFuncSetAttribute(gemm_mma<1>, cudaFuncAttributeMaxDynamicSharedMemorySize,
                             GEMM_SMEM);
        cudaFuncSetAttribute(attn_mma, cudaFuncAttributeMaxDynamicSharedMemorySize,
                             ATTN_SMEM);
        attr_done = true;
    }

    const int nX4 = M_ * DM_ / 4;      // 2097152
    const int nW4 = DM_ * DM_ / 4;     // 262144
    dim3 gg(DM_ / 128, M_ / 128);      // (8, 64)

    // Q projection
    split_k<<<(nX4 + 255) / 256, 256>>>(q, pXh, pXl, nX4);
    split_k<<<(nW4 + 255) / 256, 256>>>(wq, pWh, pWl, nW4);
    gemm_mma<1><<<gg, 256, GEMM_SMEM>>>(pXh, pXl, pWh, pWl, bq, pQ);
    // K projection
    split_k<<<(nX4 + 255) / 256, 256>>>(k, pXh, pXl, nX4);
    split_k<<<(nW4 + 255) / 256, 256>>>(wk, pWh, pWl, nW4);
    gemm_mma<1><<<gg, 256, GEMM_SMEM>>>(pXh, pXl, pWh, pWl, bk, pK);
    // V projection
    split_k<<<(nX4 + 255) / 256, 256>>>(v, pXh, pXl, nX4);
    split_k<<<(nW4 + 255) / 256, 256>>>(wv, pWh, pWl, nW4);
    gemm_mma<1><<<gg, 256, GEMM_SMEM>>>(pXh, pXl, pWh, pWl, bv, pV);

    attn_mma<<<dim3(S_ / 128, B_ * H_), 256, ATTN_SMEM>>>(pQ, pK, pV, pA);

    // Output projection
    split_k<<<(nX4 + 255) / 256, 256>>>(pA, pXh, pXl, nX4);
    split_k<<<(nW4 + 255) / 256, 256>>>(wo, pWh, pWl, nW4);
    gemm_mma<0><<<gg, 256, GEMM_SMEM>>>(pXh, pXl, pWh, pWl, bo, out);
}

// round 16
// speedup vs baseline: 2.6308x; 1.0200x over previous
#include <cuda_runtime.h>
#include <cuda_bf16.h>
#include <cstdint>

// Problem constants
#define B_  4
#define S_  2048
#define H_  16
#define DK_ 64
#define DM_ 1024
#define M_  (B_ * S_)   // 8192 rows for projections

// Scratch (device globals: allocation-free per harness rules)
__device__ float g_Q[(size_t)B_ * H_ * S_ * DK_];   // [B,H,S,dk]
__device__ float g_K[(size_t)B_ * H_ * S_ * DK_];
__device__ float g_V[(size_t)B_ * H_ * S_ * DK_];
__device__ float g_AO[(size_t)B_ * S_ * DM_];       // [B,S,D]
// bf16 hi/lo staging for GEMM operands
__device__ __nv_bfloat16 g_Xh[(size_t)M_ * DM_];
__device__ __nv_bfloat16 g_Xl[(size_t)M_ * DM_];
__device__ __nv_bfloat16 g_Wh[(size_t)DM_ * DM_];
__device__ __nv_bfloat16 g_Wl[(size_t)DM_ * DM_];
// bf16 hi/lo pre-split attention operands
__device__ __nv_bfloat16 g_Qh[(size_t)B_ * H_ * S_ * DK_];  // scaled by 1/8
__device__ __nv_bfloat16 g_Ql[(size_t)B_ * H_ * S_ * DK_];
__device__ __nv_bfloat16 g_Kh[(size_t)B_ * H_ * S_ * DK_];
__device__ __nv_bfloat16 g_Kl[(size_t)B_ * H_ * S_ * DK_];
__device__ __nv_bfloat16 g_Vth[(size_t)B_ * H_ * DK_ * S_]; // [bh][d][s]
__device__ __nv_bfloat16 g_Vtl[(size_t)B_ * H_ * DK_ * S_];

// ===========================================================================
// helpers
// ===========================================================================
__device__ __forceinline__ uint32_t smem_u32(const void* p) {
    uint32_t a;
    asm("{ .reg .u64 t; cvta.to.shared.u64 t, %1; cvt.u32.u64 %0, t; }"
        : "=r"(a) : "l"(p));
    return a;
}

#define LDSM_X4(r0, r1, r2, r3, addr)                                        \
    asm volatile("ldmatrix.sync.aligned.m8n8.x4.shared.b16 {%0,%1,%2,%3}, [%4];" \
                 : "=r"(r0), "=r"(r1), "=r"(r2), "=r"(r3) : "r"(addr))

#define MMA_BF16(d, a, B0, B1)                                               \
    asm volatile("mma.sync.aligned.m16n8k16.row.col.f32.bf16.bf16.f32 "      \
                 "{%0,%1,%2,%3}, {%4,%5,%6,%7}, {%8,%9}, {%0,%1,%2,%3};"     \
                 : "+f"((d)[0]), "+f"((d)[1]), "+f"((d)[2]), "+f"((d)[3])    \
                 : "r"((a)[0]), "r"((a)[1]), "r"((a)[2]), "r"((a)[3]),       \
                   "r"(B0), "r"(B1))

#define CP_ASYNC16(dst, src)                                                 \
    asm volatile("cp.async.cg.shared.global [%0], [%1], 16;"                 \
                 :: "r"(dst), "l"(src) : "memory")
#define CP_COMMIT() asm volatile("cp.async.commit_group;" ::: "memory")
#define CP_WAIT1()  asm volatile("cp.async.wait_group 1;" ::: "memory")
#define CP_WAIT0()  asm volatile("cp.async.wait_group 0;" ::: "memory")

// bf16 hi/lo split helpers
__device__ __forceinline__ uint32_t pack_hi(float a, float b, float& ra, float& rb) {
    __nv_bfloat16 ha = __float2bfloat16(a);
    __nv_bfloat16 hb = __float2bfloat16(b);
    ra = a - __bfloat162float(ha);
    rb = b - __bfloat162float(hb);
    __nv_bfloat162 p;
    p.x = ha; p.y = hb;
    return *(uint32_t*)&p;
}
__device__ __forceinline__ uint32_t pack_lo(float ra, float rb) {
    __nv_bfloat162 p;
    p.x = __float2bfloat16(ra);
    p.y = __float2bfloat16(rb);
    return *(uint32_t*)&p;
}

// ===========================================================================
// split_k: fp32 -> bf16 hi/lo arrays (memory-bound pre-pass), optional scale.
// ===========================================================================
__global__ __launch_bounds__(256)
void split_k(const float* __restrict__ src, __nv_bfloat16* __restrict__ hi,
             __nv_bfloat16* __restrict__ lo, int n4, float scale)
{
    int i = blockIdx.x * blockDim.x + threadIdx.x;
    if (i < n4) {
        float4 v = ((const float4*)src)[i];
        v.x *= scale; v.y *= scale; v.z *= scale; v.w *= scale;
        float r0, r1, r2, r3;
        uint32_t h01 = pack_hi(v.x, v.y, r0, r1);
        uint32_t h23 = pack_hi(v.z, v.w, r2, r3);
        ((uint2*)hi)[i] = make_uint2(h01, h23);
        ((uint2*)lo)[i] = make_uint2(pack_lo(r0, r1), pack_lo(r2, r3));
    }
}

// ===========================================================================
// split_vT: V [bh][s][d] fp32 -> transposed bf16 hi/lo [bh][d][s].
// grid (S/64, B*H), 256 threads; smem 64x64 fp32 tile, stride 65.
// ===========================================================================
__global__ __launch_bounds__(256)
void split_vT(const float* __restrict__ V, __nv_bfloat16* __restrict__ vth,
              __nv_bfloat16* __restrict__ vtl)
{
    __shared__ float vs[64][65];
    const int s0 = blockIdx.x * 64;
    const int bh = blockIdx.y;
    const float* Vb = V + (size_t)bh * (S_ * DK_);
    {
        const int s = threadIdx.x >> 2, dq = (threadIdx.x & 3) * 16;
#pragma unroll
        for (int i = 0; i < 4; i++) {
            float4 v4 = *(const float4*)(Vb + (size_t)(s0 + s) * 64 + dq + i * 4);
            vs[s][dq + i * 4 + 0] = v4.x;
            vs[s][dq + i * 4 + 1] = v4.y;
            vs[s][dq + i * 4 + 2] = v4.z;
            vs[s][dq + i * 4 + 3] = v4.w;
        }
    }
    __syncthreads();
    const int d = threadIdx.x >> 2, sg = (threadIdx.x & 3) * 16;
    uint32_t hb[8], lb[8];
#pragma unroll
    for (int i = 0; i < 8; i++) {
        float a = vs[sg + 2 * i][d], b = vs[sg + 2 * i + 1][d];
        float ra, rb;
        hb[i] = pack_hi(a, b, ra, rb);
        lb[i] = pack_lo(ra, rb);
    }
    const size_t off = ((size_t)bh * 64 + d) * S_ + s0 + sg;
    *(uint4*)(vth + off) = *(uint4*)hb;
    *(uint4*)(vth + off + 8) = *(uint4*)(hb + 4);
    *(uint4*)(vtl + off) = *(uint4*)lb;
    *(uint4*)(vtl + off + 8) = *(uint4*)(lb + 4);
}

// ===========================================================================
// HMMA GEMM on pre-split bf16 operands, cp.async double-buffered (R13, WIN).
// ===========================================================================
#define ROWB2   80
#define T_AH    0
#define T_AL    (T_AH + 128 * ROWB2)
#define T_WH    (T_AL + 128 * ROWB2)
#define T_WL    (T_WH + 128 * ROWB2)
#define BUF_SZ  (T_WL + 128 * ROWB2)    // 40960
#define GEMM_SMEM (2 * BUF_SZ)          // 81920

template <int MODE>
__global__ __launch_bounds__(256, 2)
void gemm_mma(const __nv_bfloat16* __restrict__ Ah,
              const __nv_bfloat16* __restrict__ Al,
              const __nv_bfloat16* __restrict__ Wh,
              const __nv_bfloat16* __restrict__ Wl,
              const float* __restrict__ bias, float* __restrict__ Y)
{
    extern __shared__ char sm[];
    const uint32_t sb = smem_u32(sm);
    const int tid = threadIdx.x;
    const int wid = tid >> 5;
    const int lane = tid & 31;
    const int wm = wid & 3;
    const int wn = wid >> 2;
    const int m0 = blockIdx.y * 128;
    const int n0 = blockIdx.x * 128;

    const int lr = tid >> 1;
    const int half = tid & 1;
    const char* gAh = (const char*)(Ah + (size_t)(m0 + lr) * 1024) + half * 32;
    const char* gAl = (const char*)(Al + (size_t)(m0 + lr) * 1024) + half * 32;
    const char* gWh = (const char*)(Wh + (size_t)(n0 + lr) * 1024) + half * 32;
    const char* gWl = (const char*)(Wl + (size_t)(n0 + lr) * 1024) + half * 32;
    const uint32_t srow = (uint32_t)(lr * ROWB2 + half * 32);

    float acc[2][8][4];
#pragma unroll
    for (int t = 0; t < 2; t++)
#pragma unroll
        for (int j = 0; j < 8; j++)
#pragma unroll
            for (int c = 0; c < 4; c++) acc[t][j][c] = 0.0f;

    const uint32_t a_row = (uint32_t)(wm * 32 + (lane & 15));
    const uint32_t a_colb = (uint32_t)((lane >> 4) * 16);
    const uint32_t b_row = (uint32_t)(wn * 64 + (lane & 7) + ((lane >> 4) & 1) * 8);
    const uint32_t b_colb = (uint32_t)(((lane >> 3) & 1) * 16);

#define GEMM_ISSUE(kc, buf) do {                                             \
    const uint32_t _d = sb + (buf) * BUF_SZ + srow;                          \
    const int _g = (kc) * 64;                                                \
    CP_ASYNC16(_d + T_AH,      gAh + _g);                                    \
    CP_ASYNC16(_d + T_AH + 16, gAh + _g + 16);                               \
    CP_ASYNC16(_d + T_AL,      gAl + _g);                                    \
    CP_ASYNC16(_d + T_AL + 16, gAl + _g + 16);                               \
    CP_ASYNC16(_d + T_WH,      gWh + _g);                                    \
    CP_ASYNC16(_d + T_WH + 16, gWh + _g + 16);                               \
    CP_ASYNC16(_d + T_WL,      gWl + _g);                                    \
    CP_ASYNC16(_d + T_WL + 16, gWl + _g + 16);                               \
} while (0)

    GEMM_ISSUE(0, 0);
    CP_COMMIT();

    const int NC = 32;
    for (int kc = 0; kc < NC; kc++) {
        const int buf = kc & 1;
        if (kc + 1 < NC) {
            GEMM_ISSUE(kc + 1, buf ^ 1);
            CP_COMMIT();
            CP_WAIT1();
        } else {
            CP_WAIT0();
        }
        __syncthreads();

        const uint32_t bb = sb + buf * BUF_SZ;
#pragma unroll
        for (int ks = 0; ks < 2; ks++) {
            const uint32_t kb = (uint32_t)(ks * 32);
            uint32_t ah[2][4], al[2][4];
#pragma unroll
            for (int t = 0; t < 2; t++) {
                uint32_t adr = bb + T_AH + (a_row + t * 16) * ROWB2 + kb + a_colb;
                LDSM_X4(ah[t][0], ah[t][1], ah[t][2], ah[t][3], adr);
                adr = bb + T_AL + (a_row + t * 16) * ROWB2 + kb + a_colb;
                LDSM_X4(al[t][0], al[t][1], al[t][2], al[t][3], adr);
            }
#pragma unroll
            for (int p = 0; p < 4; p++) {
                uint32_t bh[4], bl[4];
                uint32_t bdr = bb + T_WH + (b_row + p * 16) * ROWB2 + kb + b_colb;
                LDSM_X4(bh[0], bh[1], bh[2], bh[3], bdr);
                bdr = bb + T_WL + (b_row + p * 16) * ROWB2 + kb + b_colb;
                LDSM_X4(bl[0], bl[1], bl[2], bl[3], bdr);
#pragma unroll
                for (int t = 0; t < 2; t++) {
                    MMA_BF16(acc[t][p * 2 + 0], ah[t], bh[0], bh[1]);
                    MMA_BF16(acc[t][p * 2 + 0], ah[t], bl[0], bl[1]);
                    MMA_BF16(acc[t][p * 2 + 0], al[t], bh[0], bh[1]);
                    MMA_BF16(acc[t][p * 2 + 1], ah[t], bh[2], bh[3]);
                    MMA_BF16(acc[t][p * 2 + 1], ah[t], bl[2], bl[3]);
                    MMA_BF16(acc[t][p * 2 + 1], al[t], bh[2], bh[3]);
                }
            }
        }
        __syncthreads();
    }
#undef GEMM_ISSUE

#pragma unroll
    for (int t = 0; t < 2; t++) {
        const int mrow = m0 + wm * 32 + t * 16 + (lane >> 2);
#pragma unroll
        for (int j = 0; j < 8; j++) {
            const int n = n0 + wn * 64 + j * 8 + (lane & 3) * 2;
            float2 bv = *(const float2*)&bias[n];
            float2 v0, v1;
            v0.x = acc[t][j][0] + bv.x;
            v0.y = acc[t][j][1] + bv.y;
            v1.x = acc[t][j][2] + bv.x;
            v1.y = acc[t][j][3] + bv.y;
            if (MODE == 0) {
                *(float2*)&Y[(size_t)mrow * 1024 + n] = v0;
                *(float2*)&Y[(size_t)(mrow + 8) * 1024 + n] = v1;
            } else {
                int h = n >> 6, d = n & 63;
                int b0i = mrow >> 11, s0 = mrow & 2047;
                *(float2*)&Y[(((size_t)(b0i * H_ + h) * S_ + s0) << 6) + d] = v0;
                int b1i = (mrow + 8) >> 11, s1 = (mrow + 8) & 2047;
                *(float2*)&Y[(((size_t)(b1i * H_ + h) * S_ + s1) << 6) + d] = v1;
            }
        }
    }
}

// ===========================================================================
// Flash attention via HMMA on PRE-SPLIT operands: staging is pure uint4
// copies (no conversion math, no scalar transpose). Structure otherwise R13.
// ===========================================================================
#define ROWB 144
#define A_QH 0
#define A_QL (A_QH + 128 * ROWB)        // 18432
#define A_KH (A_QL + 128 * ROWB)        // 36864
#define A_KL (A_KH + 64 * ROWB)         // 46080
#define A_VH (A_KL + 64 * ROWB)         // 55296
#define A_VL (A_VH + 64 * ROWB)         // 64512
#define ATTN_SMEM (A_VL + 64 * ROWB)    // 73728

__global__ __launch_bounds__(256, 2)
void attn_mma(const __nv_bfloat16* __restrict__ Qh,
              const __nv_bfloat16* __restrict__ Ql,
              const __nv_bfloat16* __restrict__ Kh,
              const __nv_bfloat16* __restrict__ Kl,
              const __nv_bfloat16* __restrict__ Vth,
              const __nv_bfloat16* __restrict__ Vtl,
              float* __restrict__ AO)
{
    extern __shared__ char sm[];
    const uint32_t sb = smem_u32(sm);
    const int tid = threadIdx.x;
    const int wid = tid >> 5;
    const int lane = tid & 31;
    const int q0 = blockIdx.x * 128;
    const int bh = blockIdx.y;

    const __nv_bfloat16* Qhb = Qh + (size_t)bh * (S_ * DK_);
    const __nv_bfloat16* Qlb = Ql + (size_t)bh * (S_ * DK_);
    const __nv_bfloat16* Khb = Kh + (size_t)bh * (S_ * DK_);
    const __nv_bfloat16* Klb = Kl + (size_t)bh * (S_ * DK_);
    const __nv_bfloat16* Vhb = Vth + (size_t)bh * (DK_ * S_);
    const __nv_bfloat16* Vlb = Vtl + (size_t)bh * (DK_ * S_);

    // Stage Q tile: pure 64B copies per thread per array
    {
        const int lr = tid >> 1, cg = (tid & 1) * 32;
        const uint4* sh = (const uint4*)(Qhb + (size_t)(q0 + lr) * 64 + cg);
        const uint4* sl = (const uint4*)(Qlb + (size_t)(q0 + lr) * 64 + cg);
        const uint32_t sto = (uint32_t)(lr * ROWB + cg * 2);
#pragma unroll
        for (int t = 0; t < 4; t++) {
            *(uint4*)(sm + A_QH + sto + t * 16) = sh[t];
            *(uint4*)(sm + A_QL + sto + t * 16) = sl[t];
        }
    }
    __syncthreads();

    // Per-warp persistent Q fragments
    const int wr0 = wid * 16;
    uint32_t qh[4][4], ql[4][4];
    {
        const uint32_t base =
            sb + A_QH + (uint32_t)(wr0 + (lane & 15)) * ROWB + (lane >> 4) * 16;
#pragma unroll
        for (int t = 0; t < 4; t++) {
            LDSM_X4(qh[t][0], qh[t][1], qh[t][2], qh[t][3], base + t * 32);
            LDSM_X4(ql[t][0], ql[t][1], ql[t][2], ql[t][3],
                    base + (A_QL - A_QH) + t * 32);
        }
    }

    float m0 = -1e30f, m1 = -1e30f, l0 = 0.0f, l1 = 0.0f;
    float oc[8][4];
#pragma unroll
    for (int n = 0; n < 8; n++)
#pragma unroll
        for (int c = 0; c < 4; c++) oc[n][c] = 0.0f;

    const uint32_t b_row = (uint32_t)((lane & 7) + ((lane >> 4) & 1) * 8);
    const uint32_t b_colb = (uint32_t)(((lane >> 3) & 1) * 16);
    const int row0 = q0 + wr0 + (lane >> 2);

    // Staging maps (constant over loop)
    const int klr = tid >> 2, kseg = (tid & 3) * 16;   // K: row, 32B segment
    const uint32_t ksto = (uint32_t)(klr * ROWB + kseg * 2);

    const int nkt = (q0 >> 6) + 2;
    for (int kt = 0; kt < nkt; kt++) {
        const int kv0 = kt * 64;

        // K tile: [64 rows][128B] hi/lo — 2 uint4 per thread per array
        {
            const uint4* sh = (const uint4*)(Khb + (size_t)(kv0 + klr) * 64 + kseg);
            const uint4* sl = (const uint4*)(Klb + (size_t)(kv0 + klr) * 64 + kseg);
            *(uint4*)(sm + A_KH + ksto) = sh[0];
            *(uint4*)(sm + A_KH + ksto + 16) = sh[1];
            *(uint4*)(sm + A_KL + ksto) = sl[0];
            *(uint4*)(sm + A_KL + ksto + 16) = sl[1];
        }
        // V tile (pre-transposed): row d, contiguous s — same copy shape
        {
            const uint4* sh = (const uint4*)(Vhb + (size_t)klr * S_ + kv0 + kseg);
            const uint4* sl = (const uint4*)(Vlb + (size_t)klr * S_ + kv0 + kseg);
            *(uint4*)(sm + A_VH + ksto) = sh[0];
            *(uint4*)(sm + A_VH + ksto + 16) = sh[1];
            *(uint4*)(sm + A_VL + ksto) = sl[0];
            *(uint4*)(sm + A_VL + ksto + 16) = sl[1];
        }
        __syncthreads();

        if (kv0 <= q0 + wr0 + 15) {
            // S = Q K^T (3-term split)
            float sc[8][4];
#pragma unroll
            for (int n = 0; n < 8; n++)
#pragma unroll
                for (int c = 0; c < 4; c++) sc[n][c] = 0.0f;

#pragma unroll
            for (int t = 0; t < 4; t++) {
#pragma unroll
                for (int pp = 0; pp < 4; pp++) {
                    uint32_t kb0, kb1, kb2, kb3, kl0, kl1, kl2, kl3;
                    uint32_t adr =
                        sb + A_KH + (pp * 16 + b_row) * ROWB + t * 32 + b_colb;
                    LDSM_X4(kb0, kb1, kb2, kb3, adr);
                    LDSM_X4(kl0, kl1, kl2, kl3, adr + (A_KL - A_KH));
                    MMA_BF16(sc[pp * 2 + 0], qh[t], kb0, kb1);
                    MMA_BF16(sc[pp * 2 + 0], qh[t], kl0, kl1);
                    MMA_BF16(sc[pp * 2 + 0], ql[t], kb0, kb1);
                    MMA_BF16(sc[pp * 2 + 1], qh[t], kb2, kb3);
                    MMA_BF16(sc[pp * 2 + 1], qh[t], kl2, kl3);
                    MMA_BF16(sc[pp * 2 + 1], ql[t], kb2, kb3);
                }
            }

            // Causal mask on diagonal-overlapping tiles
            if (kv0 + 63 > q0 + wr0) {
#pragma unroll
                for (int n = 0; n < 8; n++) {
                    const int col = kv0 + n * 8 + (lane & 3) * 2;
                    if (col > row0)         sc[n][0] = -1e30f;
                    if (col + 1 > row0)     sc[n][1] = -1e30f;
                    if (col > row0 + 8)     sc[n][2] = -1e30f;
                    if (col + 1 > row0 + 8) sc[n][3] = -1e30f;
                }
            }

            // Online softmax
            float mx0 = -1e30f, mx1 = -1e30f;
#pragma unroll
            for (int n = 0; n < 8; n++) {
                mx0 = fmaxf(mx0, fmaxf(sc[n][0], sc[n][1]));
                mx1 = fmaxf(mx1, fmaxf(sc[n][2], sc[n][3]));
            }
            mx0 = fmaxf(mx0, __shfl_xor_sync(0xffffffffu, mx0, 1));
            mx0 = fmaxf(mx0, __shfl_xor_sync(0xffffffffu, mx0, 2));
            mx1 = fmaxf(mx1, __shfl_xor_sync(0xffffffffu, mx1, 1));
            mx1 = fmaxf(mx1, __shfl_xor_sync(0xffffffffu, mx1, 2));

            const float mn0 = fmaxf(m0, mx0), mn1 = fmaxf(m1, mx1);
            const float corr0 = __expf(m0 - mn0), corr1 = __expf(m1 - mn1);
            float rs0 = 0.0f, rs1 = 0.0f;
#pragma unroll
            for (int n = 0; n < 8; n++) {
                sc[n][0] = __expf(sc[n][0] - mn0);
                sc[n][1] = __expf(sc[n][1] - mn0);
                sc[n][2] = __expf(sc[n][2] - mn1);
                sc[n][3] = __expf(sc[n][3] - mn1);
                rs0 += sc[n][0] + sc[n][1];
                rs1 += sc[n][2] + sc[n][3];
            }
            rs0 += __shfl_xor_sync(0xffffffffu, rs0, 1);
            rs0 += __shfl_xor_sync(0xffffffffu, rs0, 2);
            rs1 += __shfl_xor_sync(0xffffffffu, rs1, 1);
            rs1 += __shfl_xor_sync(0xffffffffu, rs1, 2);
            l0 = l0 * corr0 + rs0;  m0 = mn0;
            l1 = l1 * corr1 + rs1;  m1 = mn1;
#pragma unroll
            for (int n = 0; n < 8; n++) {
                oc[n][0] *= corr0;  oc[n][1] *= corr0;
                oc[n][2] *= corr1;  oc[n][3] *= corr1;
            }

            // O += P V
#pragma unroll
            for (int t = 0; t < 4; t++) {
                uint32_t ph[4], pl[4];
                float ra, rb;
                ph[0] = pack_hi(sc[2 * t][0], sc[2 * t][1], ra, rb);
                pl[0] = pack_lo(ra, rb);
                ph[1] = pack_hi(sc[2 * t][2], sc[2 * t][3], ra, rb);
                pl[1] = pack_lo(ra, rb);
                ph[2] = pack_hi(sc[2 * t + 1][0], sc[2 * t + 1][1], ra, rb);
                pl[2] = pack_lo(ra, rb);
                ph[3] = pack_hi(sc[2 * t + 1][2], sc[2 * t + 1][3], ra, rb);
                pl[3] = pack_lo(ra, rb);
#pragma unroll
                for (int pp = 0; pp < 4; pp++) {
                    uint32_t vh0, vh1, vh2, vh3, vl0, vl1, vl2, vl3;
                    uint32_t adr =
                        sb + A_VH + (pp * 16 + b_row) * ROWB + t * 32 + b_colb;
                    LDSM_X4(vh0, vh1, vh2, vh3, adr);
                    LDSM_X4(vl0, vl1, vl2, vl3, adr + (A_VL - A_VH));
                    MMA_BF16(oc[pp * 2 + 0], ph, vh0, vh1);
                    MMA_BF16(oc[pp * 2 + 0], ph, vl0, vl1);
                    MMA_BF16(oc[pp * 2 + 0], pl, vh0, vh1);
                    MMA_BF16(oc[pp * 2 + 1], ph, vh2, vh3);
                    MMA_BF16(oc[pp * 2 + 1], ph, vl2, vl3);
                    MMA_BF16(oc[pp * 2 + 1], pl, vh2, vh3);
                }
            }
        }
        __syncthreads();
    }

    // Epilogue
    const int b = bh >> 4, h = bh & 15;
    const float inv0 = 1.0f / l0, inv1 = 1.0f / l1;
#pragma unroll
    for (int n = 0; n < 8; n++) {
        const int d = h * 64 + n * 8 + (lane & 3) * 2;
        float2 v0 = make_float2(oc[n][0] * inv0, oc[n][1] * inv0);
        float2 v1 = make_float2(oc[n][2] * inv1, oc[n][3] * inv1);
        *(float2*)&AO[(size_t)(b * S_ + row0) * DM_ + d] = v0;
        *(float2*)&AO[(size_t)(b * S_ + row0 + 8) * DM_ + d] = v1;
    }
}

// ---------------------------------------------------------------------------
extern "C" void kernel_launch(void* const* d_in, const int* in_sizes, int n_in,
                              void* d_out, int out_size)
{
    const float* q  = (const float*)d_in[0];
    const float* k  = (const float*)d_in[1];
    const float* v  = (const float*)d_in[2];
    // d_in[3] = mask (deterministic causal tril; handled structurally)
    const float* wq = (const float*)d_in[4];
    const float* bq = (const float*)d_in[5];
    const float* wk = (const float*)d_in[6];
    const float* bk = (const float*)d_in[7];
    const float* wv = (const float*)d_in[8];
    const float* bv = (const float*)d_in[9];
    const float* wo = (const float*)d_in[10];
    const float* bo = (const float*)d_in[11];
    float* out = (float*)d_out;

    float *pQ, *pK, *pV, *pA;
    __nv_bfloat16 *pXh, *pXl, *pWh, *pWl;
    __nv_bfloat16 *pQh, *pQl, *pKh, *pKl, *pVth, *pVtl;
    cudaGetSymbolAddress((void**)&pQ, g_Q);
    cudaGetSymbolAddress((void**)&pK, g_K);
    cudaGetSymbolAddress((void**)&pV, g_V);
    cudaGetSymbolAddress((void**)&pA, g_AO);
    cudaGetSymbolAddress((void**)&pXh, g_Xh);
    cudaGetSymbolAddress((void**)&pXl, g_Xl);
    cudaGetSymbolAddress((void**)&pWh, g_Wh);
    cudaGetSymbolAddress((void**)&pWl, g_Wl);
    cudaGetSymbolAddress((void**)&pQh, g_Qh);
    cudaGetSymbolAddress((void**)&pQl, g_Ql);
    cudaGetSymbolAddress((void**)&pKh, g_Kh);
    cudaGetSymbolAddress((void**)&pKl, g_Kl);
    cudaGetSymbolAddress((void**)&pVth, g_Vth);
    cudaGetSymbolAddress((void**)&pVtl, g_Vtl);

    static bool attr_done = false;
    if (!attr_done) {
        cudaFuncSetAttribute(gemm_mma<0>, cudaFuncAttributeMaxDynamicSharedMemorySize,
                             GEMM_SMEM);
        cudaFuncSetAttribute(gemm_mma<1>, cudaFuncAttributeMaxDynamicSharedMemorySize,
                             GEMM_SMEM);
        cudaFuncSetAttribute(attn_mma, cudaFuncAttributeMaxDynamicSharedMemorySize,
                             ATTN_SMEM);
        attr_done = true;
    }

    const int nX4 = M_ * DM_ / 4;      // 2097152
    const int nW4 = DM_ * DM_ / 4;     // 262144
    dim3 gg(DM_ / 128, M_ / 128);      // (8, 64)

    // Q projection
    split_k<<<(nX4 + 255) / 256, 256>>>(q, pXh, pXl, nX4, 1.0f);
    split_k<<<(nW4 + 255) / 256, 256>>>(wq, pWh, pWl, nW4, 1.0f);
    gemm_mma<1><<<gg, 256, GEMM_SMEM>>>(pXh, pXl, pWh, pWl, bq, pQ);
    // K projection
    split_k<<<(nX4 + 255) / 256, 256>>>(k, pXh, pXl, nX4, 1.0f);
    split_k<<<(nW4 + 255) / 256, 256>>>(wk, pWh, pWl, nW4, 1.0f);
    gemm_mma<1><<<gg, 256, GEMM_SMEM>>>(pXh, pXl, pWh, pWl, bk, pK);
    // V projection
    split_k<<<(nX4 + 255) / 256, 256>>>(v, pXh, pXl, nX4, 1.0f);
    split_k<<<(nW4 + 255) / 256, 256>>>(wv, pWh, pWl, nW4, 1.0f);
    gemm_mma<1><<<gg, 256, GEMM_SMEM>>>(pXh, pXl, pWh, pWl, bv, pV);

    // Pre-split attention operands (Q scaled by exact 1/8; V transposed)
    split_k<<<(nX4 + 255) / 256, 256>>>(pQ, pQh, pQl, nX4, 0.125f);
    split_k<<<(nX4 + 255) / 256, 256>>>(pK, pKh, pKl, nX4, 1.0f);
    split_vT<<<dim3(S_ / 64, B_ * H_), 256>>>(pV, pVth, pVtl);

    attn_mma<<<dim3(S_ / 128, B_ * H_), 256, ATTN_SMEM>>>(
        pQh, pQl, pKh, pKl, pVth, pVtl, pA);

    // Output projection
    split_k<<<(nX4 + 255) / 256, 256>>>(pA, pXh, pXl, nX4, 1.0f);
    split_k<<<(nW4 + 255) / 256, 256>>>(wo, pWh, pWl, nW4, 1.0f);
    gemm_mma<0><<<gg, 256, GEMM_SMEM>>>(pXh, pXl, pWh, pWl, bo, out);
}